// round 6
// baseline (speedup 1.0000x reference)
#include <cuda_runtime.h>
#include <cuda_bf16.h>
#include <cstdint>

typedef unsigned long long ULL;

// ---------------- scratch (static device globals; no allocation) ------------
__device__ float g_y0[524288 * 64];
__device__ float g_y1[524288 * 64];
__device__ float g_maxraw[16384 * 128];
__device__ int   g_fpsidx[16384];
__device__ float g_cent[16384 * 3];
__device__ int   g_gidx[524288];
__device__ float g_Wt0[68 * 64];
__device__ float g_Wt1[64 * 64];
__device__ float g_Wt2[64 * 128];
__device__ float g_s0[64], g_q0[64], g_s1[64], g_q1[64], g_s2[128], g_q2[128];
__device__ float g_a0[64], g_c0[64], g_a1[64], g_c1[64], g_a2[128], g_c2[128];

// ---------------- helpers ---------------------------------------------------
__device__ __forceinline__ ULL packf2(float lo, float hi) {
    ULL r; unsigned a = __float_as_uint(lo), b = __float_as_uint(hi);
    asm("mov.b64 %0,{%1,%2};" : "=l"(r) : "r"(a), "r"(b)); return r;
}
__device__ __forceinline__ float2 unpackf2(ULL v) {
    unsigned a, b; asm("mov.b64 {%0,%1},%2;" : "=r"(a), "=r"(b) : "l"(v));
    return make_float2(__uint_as_float(a), __uint_as_float(b));
}
__device__ __forceinline__ ULL f2add(ULL a, ULL b) {
    ULL r; asm("add.rn.f32x2 %0,%1,%2;" : "=l"(r) : "l"(a), "l"(b)); return r;
}
__device__ __forceinline__ ULL f2mul(ULL a, ULL b) {
    ULL r; asm("mul.rn.f32x2 %0,%1,%2;" : "=l"(r) : "l"(a), "l"(b)); return r;
}
__device__ __forceinline__ ULL f2fma(ULL a, ULL b, ULL c) {
    ULL r; asm("fma.rn.f32x2 %0,%1,%2,%3;" : "=l"(r) : "l"(a), "l"(b), "l"(c)); return r;
}
__device__ __forceinline__ float d2_noFMA(float dx, float dy, float dz) {
    return __fadd_rn(__fadd_rn(__fmul_rn(dx, dx), __fmul_rn(dy, dy)), __fmul_rn(dz, dz));
}

// ---------------- zero stats -------------------------------------------------
__global__ void zero_k() {
    int t = threadIdx.x;
    if (t < 64) { g_s0[t]=0.f; g_q0[t]=0.f; g_s1[t]=0.f; g_q1[t]=0.f; }
    if (t < 128){ g_s2[t]=0.f; g_q2[t]=0.f; }
}

// ---------------- FPS: 1 CTA/batch, 512 thr, 16 pts/thread, 2 barriers ------
__global__ void __launch_bounds__(512) fps_k(const float* __restrict__ xyz) {
    extern __shared__ float sx[];                      // 24576 floats
    __shared__ unsigned swhi[16], swlo[16];
    __shared__ unsigned s_p;
    const int b = blockIdx.x, tid = threadIdx.x, wid = tid >> 5, lane = tid & 31;
    const float* X = xyz + (size_t)b * 24576;

    for (int i = tid; i < 6144; i += 512)
        ((float4*)sx)[i] = ((const float4*)X)[i];
    __syncthreads();

    ULL px[8], py[8], pz[8]; float dist[16];
#pragma unroll
    for (int j = 0; j < 8; j++) {
        int p0 = tid + 1024 * j, p1 = p0 + 512;
        px[j] = packf2(sx[3*p0+0], sx[3*p1+0]);
        py[j] = packf2(sx[3*p0+1], sx[3*p1+1]);
        pz[j] = packf2(sx[3*p0+2], sx[3*p1+2]);
        dist[2*j] = 1e10f; dist[2*j+1] = 1e10f;
    }
    float cx = sx[0], cy = sx[1], cz = sx[2];
    if (tid == 0) g_fpsidx[b * 2048] = 0;

    for (int s = 1; s < 2048; s++) {
        ULL ncx = packf2(-cx, -cx), ncy = packf2(-cy, -cy), ncz = packf2(-cz, -cz);
        float m8 = 0.0f;
#pragma unroll
        for (int j = 0; j < 8; j++) {
            ULL dx = f2add(px[j], ncx);
            ULL dy = f2add(py[j], ncy);
            ULL dz = f2add(pz[j], ncz);
            // mul/add tree, no FMA: matches reference rounding exactly
            ULL d2 = f2add(f2add(f2mul(dx, dx), f2mul(dy, dy)), f2mul(dz, dz));
            float2 d = unpackf2(d2);
            float a = fminf(dist[2*j],   d.x); dist[2*j]   = a;
            float c = fminf(dist[2*j+1], d.y); dist[2*j+1] = c;
            m8 = fmaxf(m8, fmaxf(a, c));
        }
        unsigned mb = __float_as_uint(m8);               // dists >= 0: bit-monotone
        unsigned wm = __reduce_max_sync(0xffffffffu, mb);
        unsigned cand = 0xffffffffu;
        if (mb == wm) {
#pragma unroll
            for (int i = 0; i < 16; i++) {
                if (__float_as_uint(dist[i]) == wm) { cand = (unsigned)(tid + (i << 9)); break; }
            }
        }
        unsigned cmin = __reduce_min_sync(0xffffffffu, cand);
        if (lane == 0) { swhi[wid] = wm; swlo[wid] = cmin; }
        __syncthreads();
        if (wid == 0) {
            unsigned hi = (lane < 16) ? swhi[lane] : 0u;
            unsigned lo = (lane < 16) ? swlo[lane] : 0xffffffffu;
            unsigned hm = __reduce_max_sync(0xffffffffu, hi);
            unsigned lm = __reduce_min_sync(0xffffffffu, (hi == hm) ? lo : 0xffffffffu);
            if (lane == 0) s_p = lm;
        }
        __syncthreads();
        unsigned p = s_p;
        if (tid == 0) g_fpsidx[b * 2048 + s] = (int)p;
        cx = sx[3*p]; cy = sx[3*p+1]; cz = sx[3*p+2];
    }
}

// ---------------- centroids --------------------------------------------------
__global__ void centroid_k(const float* __restrict__ xyz, float* __restrict__ outc) {
    int id = blockIdx.x * 256 + threadIdx.x;
    if (id >= 16384) return;
    int b = id >> 11;
    int p = g_fpsidx[id];
    const float* src = xyz + ((size_t)(b << 13) + p) * 3;
    float x = src[0], y = src[1], z = src[2];
    outc[id*3+0] = x; outc[id*3+1] = y; outc[id*3+2] = z;
    g_cent[id*3+0] = x; g_cent[id*3+1] = y; g_cent[id*3+2] = z;
}

// ---------------- ball query: smem-staged, warp per centroid -----------------
__global__ void __launch_bounds__(512) ballq_k(const float* __restrict__ xyz) {
    extern __shared__ float sb[];                      // 24576 + 512 ints
    int* sidx = (int*)(sb + 24576);
    int tid = threadIdx.x, wid = tid >> 5, lane = tid & 31;
    int cid = blockIdx.x * 16 + wid;                   // 16 centroids / CTA, same batch
    int b = cid >> 11;
    const float* X = xyz + (size_t)b * 24576;
    for (int i = tid; i < 6144; i += 512)
        ((float4*)sb)[i] = ((const float4*)X)[i];
    float cx = g_cent[cid*3], cy = g_cent[cid*3+1], cz = g_cent[cid*3+2];
    __syncthreads();

    int cnt = 0;
    for (int base = 0; base < 8192; base += 32) {
        int j = base + lane;
        float d2 = d2_noFMA(cx - sb[3*j], cy - sb[3*j+1], cz - sb[3*j+2]);
        bool hit = d2 <= 0.04f;
        unsigned m = __ballot_sync(0xffffffffu, hit);
        if (m) {
            int r = __popc(m & ((1u << lane) - 1u));
            if (hit && cnt + r < 32) sidx[wid*32 + cnt + r] = j;
            cnt += __popc(m);
            if (cnt >= 32) break;
        }
    }
    __syncwarp();
    int first = sidx[wid*32];
    int c = cnt < 32 ? cnt : 32;
    g_gidx[cid * 32 + lane] = (lane < c) ? sidx[wid*32 + lane] : first;
}

// ---------------- weight transpose (k-major) ---------------------------------
__global__ void prepw_k(const float* __restrict__ w0, const float* __restrict__ w1,
                        const float* __restrict__ w2) {
    int t = blockIdx.x * 256 + threadIdx.x;
    if (t < 68 * 64) {
        int k = t >> 6, n = t & 63;
        float v = 0.f;
        if (k < 64) v = w0[n * 67 + 3 + k];
        else if (k < 67) v = w0[n * 67 + (k - 64)];
        g_Wt0[k * 64 + n] = v;
    }
    int t1 = t - 68 * 64;
    if (t1 >= 0 && t1 < 64 * 64) {
        int k = t1 >> 6, n = t1 & 63;
        g_Wt1[k * 64 + n] = w1[n * 64 + k];
    }
    int t2 = t1 - 64 * 64;
    if (t2 >= 0 && t2 < 64 * 128) {
        int k = t2 >> 7, n = t2 & 127;
        g_Wt2[k * 128 + n] = w2[n * 64 + k];
    }
}

// ---------------- GEMM: 128-row tile, 256 thr, f32x2 packed FMA --------------
// MODE 0: gather A from (feat,xyz,cent,gidx), stats.       N=64, KP=68
// MODE 1: A from Y-prev with fused BN affine+ReLU, stats.  N=64, KP=64
// MODE 2: A fused act, epilogue = max-over-K + stats, no Y store. N=128, KP=64
template<int KP, int N, int MODE>
__global__ void __launch_bounds__(256) gemm_k(
    const float* __restrict__ A, const float* __restrict__ Wt,
    const float* __restrict__ bias,
    const float* __restrict__ fa, const float* __restrict__ fc,
    const float* __restrict__ xyz, const float* __restrict__ feat,
    float* __restrict__ Y, float* __restrict__ gs, float* __restrict__ gq)
{
    extern __shared__ float sm[];
    float* As  = sm;                 // [128][KP] row-major
    float* Bs  = sm + 128 * KP;      // [KP][N]
    float* Red = Bs + KP * N;        // partials
    const int tid = threadIdx.x;
    const size_t rb = (size_t)blockIdx.x * 128;

    for (int i = tid; i < KP * N / 4; i += 256)
        ((float4*)Bs)[i] = ((const float4*)Wt)[i];

    if (MODE == 0) {
        // gather: 17 float4 chunks per row (16 feat + 1 xyz/pad)
        for (int i = tid; i < 128 * 17; i += 256) {
            int r = i / 17, c4 = i - r * 17;
            int grow = (int)rb + r;
            int j = g_gidx[grow];
            int b = grow >> 16;
            float4 v;
            if (c4 < 16) {
                v = ((const float4*)(feat + ((size_t)(b << 13) + j) * 64))[c4];
            } else {
                const float* xp = xyz + ((size_t)(b << 13) + j) * 3;
                const float* cp = g_cent + (grow >> 5) * 3;
                v = make_float4(xp[0]-cp[0], xp[1]-cp[1], xp[2]-cp[2], 0.f);
            }
            ((float4*)(As + r * KP))[c4] = v;
        }
    } else {
        const int K4 = KP / 4;
        for (int i = tid; i < 128 * K4; i += 256) {
            int r = i / K4, c = i - r * K4;
            float4 v = ((const float4*)(A + (rb + r) * KP))[c];
            int k = c * 4;
            v.x = fmaxf(fmaf(fa[k+0], v.x, fc[k+0]), 0.f);
            v.y = fmaxf(fmaf(fa[k+1], v.y, fc[k+1]), 0.f);
            v.z = fmaxf(fmaf(fa[k+2], v.z, fc[k+2]), 0.f);
            v.w = fmaxf(fmaf(fa[k+3], v.w, fc[k+3]), 0.f);
            ((float4*)(As + r * KP))[c] = v;
        }
    }
    __syncthreads();

    // micro-tile: 4 rows (tr+32i) x NT2 cols, cols packed in pairs
    constexpr int NT2 = N / 8;                    // 8 or 16 cols/thread
    constexpr int NJ  = NT2 / 2;                  // packed pairs
    const int tc = (tid & 7) * NT2, tr = tid >> 3;  // tr 0..31
    ULL acc[4][NJ];
#pragma unroll
    for (int j2 = 0; j2 < NJ; j2++) {
        ULL bb = *(const ULL*)&bias[tc + 2*j2];
#pragma unroll
        for (int m = 0; m < 4; m++) acc[m][j2] = bb;
    }

#pragma unroll 4
    for (int k = 0; k < KP; k++) {
        ULL ap[4];
#pragma unroll
        for (int m = 0; m < 4; m++) {
            float a = As[(tr + 32*m) * KP + k];
            ap[m] = packf2(a, a);
        }
        ULL bp[NJ];
#pragma unroll
        for (int j2 = 0; j2 < NJ; j2++) bp[j2] = *(const ULL*)&Bs[k * N + tc + 2*j2];
#pragma unroll
        for (int m = 0; m < 4; m++)
#pragma unroll
            for (int j2 = 0; j2 < NJ; j2++)
                acc[m][j2] = f2fma(ap[m], bp[j2], acc[m][j2]);
    }

    if (MODE != 2) {
        // store Y
#pragma unroll
        for (int m = 0; m < 4; m++) {
            size_t row = rb + tr + 32*m;
#pragma unroll
            for (int j2 = 0; j2 < NJ; j2 += 2) {
                float2 a = unpackf2(acc[m][j2]);
                float2 b = unpackf2(acc[m][j2+1]);
                *(float4*)&Y[row * N + tc + 2*j2] = make_float4(a.x, a.y, b.x, b.y);
            }
        }
        // stats: per-col sum/sumsq -> shfl -> warp partial -> smem -> global
        float s[NT2], q[NT2];
#pragma unroll
        for (int j2 = 0; j2 < NJ; j2++) {
            float2 v0 = unpackf2(acc[0][j2]);
            float2 v1 = unpackf2(acc[1][j2]);
            float2 v2 = unpackf2(acc[2][j2]);
            float2 v3 = unpackf2(acc[3][j2]);
            s[2*j2]   = v0.x + v1.x + v2.x + v3.x;
            s[2*j2+1] = v0.y + v1.y + v2.y + v3.y;
            q[2*j2]   = fmaf(v0.x,v0.x, fmaf(v1.x,v1.x, fmaf(v2.x,v2.x, v3.x*v3.x)));
            q[2*j2+1] = fmaf(v0.y,v0.y, fmaf(v1.y,v1.y, fmaf(v2.y,v2.y, v3.y*v3.y)));
        }
#pragma unroll
        for (int j = 0; j < NT2; j++) {
            s[j] += __shfl_xor_sync(0xffffffffu, s[j], 8);
            q[j] += __shfl_xor_sync(0xffffffffu, q[j], 8);
            s[j] += __shfl_xor_sync(0xffffffffu, s[j], 16);
            q[j] += __shfl_xor_sync(0xffffffffu, q[j], 16);
        }
        int w = tid >> 5, lane = tid & 31;
        if (lane < 8) {
#pragma unroll
            for (int j = 0; j < NT2; j++) {
                Red[w * 2*N + (lane * NT2 + j)]     = s[j];
                Red[w * 2*N + N + (lane * NT2 + j)] = q[j];
            }
        }
        __syncthreads();
        if (tid < N) {
            float ss = 0.f, qq = 0.f;
#pragma unroll
            for (int ww = 0; ww < 8; ww++) {
                ss += Red[ww * 2*N + tid];
                qq += Red[ww * 2*N + N + tid];
            }
            atomicAdd(&gs[tid], ss);
            atomicAdd(&gq[tid], qq);
        }
    } else {
        // MODE 2: max over each 32-row group (m == group), plus stats
        float* smax = Red;                 // [8][4][128]
        float* ssum = Red + 8*4*128;       // [8][128]
        float* ssq  = ssum + 8*128;        // [8][128]
        float mx[4][NT2], s[NT2], q[NT2];
#pragma unroll
        for (int j = 0; j < NT2; j++) { s[j] = 0.f; q[j] = 0.f; }
#pragma unroll
        for (int m = 0; m < 4; m++)
#pragma unroll
            for (int j2 = 0; j2 < NJ; j2++) {
                float2 v = unpackf2(acc[m][j2]);
                mx[m][2*j2] = v.x; mx[m][2*j2+1] = v.y;
                s[2*j2] += v.x; s[2*j2+1] += v.y;
                q[2*j2]   = fmaf(v.x, v.x, q[2*j2]);
                q[2*j2+1] = fmaf(v.y, v.y, q[2*j2+1]);
            }
#pragma unroll
        for (int j = 0; j < NT2; j++) {
#pragma unroll
            for (int m = 0; m < 4; m++) {
                mx[m][j] = fmaxf(mx[m][j], __shfl_xor_sync(0xffffffffu, mx[m][j], 8));
                mx[m][j] = fmaxf(mx[m][j], __shfl_xor_sync(0xffffffffu, mx[m][j], 16));
            }
            s[j] += __shfl_xor_sync(0xffffffffu, s[j], 8);
            s[j] += __shfl_xor_sync(0xffffffffu, s[j], 16);
            q[j] += __shfl_xor_sync(0xffffffffu, q[j], 8);
            q[j] += __shfl_xor_sync(0xffffffffu, q[j], 16);
        }
        int w = tid >> 5, lane = tid & 31;
        if (lane < 8) {
#pragma unroll
            for (int j = 0; j < NT2; j++) {
                int c = lane * NT2 + j;
#pragma unroll
                for (int m = 0; m < 4; m++) smax[(w*4 + m) * 128 + c] = mx[m][j];
                ssum[w * 128 + c] = s[j];
                ssq[w * 128 + c]  = q[j];
            }
        }
        __syncthreads();
        for (int cell = tid; cell < 512; cell += 256) {
            int m = cell >> 7, c = cell & 127;
            float v = smax[m * 128 + c];
#pragma unroll
            for (int ww = 1; ww < 8; ww++) v = fmaxf(v, smax[(ww*4 + m) * 128 + c]);
            g_maxraw[((size_t)blockIdx.x * 4 + m) * 128 + c] = v;
        }
        if (tid < 128) {
            float ss = 0.f, qq = 0.f;
#pragma unroll
            for (int ww = 0; ww < 8; ww++) { ss += ssum[ww*128 + tid]; qq += ssq[ww*128 + tid]; }
            atomicAdd(&gs[tid], ss);
            atomicAdd(&gq[tid], qq);
        }
    }
}

// ---------------- BN affine finalize -----------------------------------------
__global__ void finalize_k(const float* __restrict__ s, const float* __restrict__ q,
                           const float* __restrict__ g, const float* __restrict__ beta,
                           float* __restrict__ fa, float* __restrict__ fc, int n) {
    int i = blockIdx.x * 64 + threadIdx.x;
    if (i < n) {
        const float inv = 1.0f / 524288.0f;
        float m = s[i] * inv;
        float var = q[i] * inv - m * m;
        float a = g[i] * rsqrtf(var + 1e-5f);
        fa[i] = a;
        fc[i] = fmaf(-m, a, beta[i]);
    }
}

// ---------------- final output ------------------------------------------------
__global__ void out_k(float* __restrict__ out) {
    int id = blockIdx.x * 256 + threadIdx.x;
    int c = id & 127;
    out[id] = fmaxf(fmaf(g_a2[c], g_maxraw[id], g_c2[c]), 0.f);
}

// ---------------- launch ------------------------------------------------------
extern "C" void kernel_launch(void* const* d_in, const int* in_sizes, int n_in,
                              void* d_out, int out_size) {
    const float* xyz  = (const float*)d_in[0];
    const float* feat = (const float*)d_in[1];
    const float* w0 = (const float*)d_in[2],  *b0 = (const float*)d_in[3];
    const float* g0 = (const float*)d_in[4],  *be0 = (const float*)d_in[5];
    const float* w1 = (const float*)d_in[6],  *b1 = (const float*)d_in[7];
    const float* g1 = (const float*)d_in[8],  *be1 = (const float*)d_in[9];
    const float* w2 = (const float*)d_in[10], *b2 = (const float*)d_in[11];
    const float* g2 = (const float*)d_in[12], *be2 = (const float*)d_in[13];
    float* out = (float*)d_out;

    float *ds0,*dq0,*ds1,*dq1,*ds2,*dq2,*da0,*dc0,*da1,*dc1,*da2,*dc2;
    cudaGetSymbolAddress((void**)&ds0, g_s0); cudaGetSymbolAddress((void**)&dq0, g_q0);
    cudaGetSymbolAddress((void**)&ds1, g_s1); cudaGetSymbolAddress((void**)&dq1, g_q1);
    cudaGetSymbolAddress((void**)&ds2, g_s2); cudaGetSymbolAddress((void**)&dq2, g_q2);
    cudaGetSymbolAddress((void**)&da0, g_a0); cudaGetSymbolAddress((void**)&dc0, g_c0);
    cudaGetSymbolAddress((void**)&da1, g_a1); cudaGetSymbolAddress((void**)&dc1, g_c1);
    cudaGetSymbolAddress((void**)&da2, g_a2); cudaGetSymbolAddress((void**)&dc2, g_c2);
    float *dy0,*dy1,*dWt0,*dWt1,*dWt2;
    cudaGetSymbolAddress((void**)&dy0, g_y0);
    cudaGetSymbolAddress((void**)&dy1, g_y1);
    cudaGetSymbolAddress((void**)&dWt0, g_Wt0);
    cudaGetSymbolAddress((void**)&dWt1, g_Wt1);
    cudaGetSymbolAddress((void**)&dWt2, g_Wt2);

    const int smemF = 24576 * 4;                     // fps
    const int smemB = 24576 * 4 + 512 * 4;           // ballq
    const int smem0 = (128*68 + 68*64 + 8*128) * 4;  // 56320
    const int smem1 = (128*64 + 64*64 + 8*128) * 4;  // 53248
    const int smem2 = (128*64 + 64*128 + 8*4*128 + 2*8*128) * 4; // 90112
    cudaFuncSetAttribute(fps_k,   cudaFuncAttributeMaxDynamicSharedMemorySize, smemF);
    cudaFuncSetAttribute(ballq_k, cudaFuncAttributeMaxDynamicSharedMemorySize, smemB);
    cudaFuncSetAttribute(gemm_k<68,64,0>,  cudaFuncAttributeMaxDynamicSharedMemorySize, smem0);
    cudaFuncSetAttribute(gemm_k<64,64,1>,  cudaFuncAttributeMaxDynamicSharedMemorySize, smem1);
    cudaFuncSetAttribute(gemm_k<64,128,2>, cudaFuncAttributeMaxDynamicSharedMemorySize, smem2);

    zero_k<<<1, 128>>>();
    fps_k<<<8, 512, smemF>>>(xyz);
    centroid_k<<<64, 256>>>(xyz, out);               // out[0..49151] = centroids
    ballq_k<<<1024, 512, smemB>>>(xyz);
    prepw_k<<<65, 256>>>(w0, w1, w2);
    gemm_k<68,64,0><<<4096, 256, smem0>>>(nullptr, dWt0, b0, nullptr, nullptr,
                                          xyz, feat, dy0, ds0, dq0);
    finalize_k<<<1, 64>>>(ds0, dq0, g0, be0, da0, dc0, 64);
    gemm_k<64,64,1><<<4096, 256, smem1>>>(dy0, dWt1, b1, da0, dc0,
                                          nullptr, nullptr, dy1, ds1, dq1);
    finalize_k<<<1, 64>>>(ds1, dq1, g1, be1, da1, dc1, 64);
    gemm_k<64,128,2><<<4096, 256, smem2>>>(dy1, dWt2, b2, da1, dc1,
                                           nullptr, nullptr, nullptr, ds2, dq2);
    finalize_k<<<2, 64>>>(ds2, dq2, g2, be2, da2, dc2, 128);
    out_k<<<8192, 256>>>(out + 49152);
}

// round 7
// speedup vs baseline: 1.1037x; 1.1037x over previous
#include <cuda_runtime.h>
#include <cuda_bf16.h>
#include <cstdint>

typedef unsigned long long ULL;

// ---------------- scratch (static device globals; no allocation) ------------
__device__ float g_y0[524288 * 64];
__device__ float g_y1[524288 * 64];
__device__ float g_y2[(size_t)524288 * 128];
__device__ float g_maxraw[16384 * 128];
__device__ int   g_fpsidx[16384];
__device__ float g_cent[16384 * 3];
__device__ int   g_gidx[524288];
__device__ float g_Wt0[68 * 64];
__device__ float g_Wt1[64 * 64];
__device__ float g_Wt2[64 * 128];
__device__ float g_s0[64], g_q0[64], g_s1[64], g_q1[64], g_s2[128], g_q2[128];
__device__ float g_a0[64], g_c0[64], g_a1[64], g_c1[64], g_a2[128], g_c2[128];

// ---------------- helpers ---------------------------------------------------
__device__ __forceinline__ ULL packf2(float lo, float hi) {
    ULL r; unsigned a = __float_as_uint(lo), b = __float_as_uint(hi);
    asm("mov.b64 %0,{%1,%2};" : "=l"(r) : "r"(a), "r"(b)); return r;
}
__device__ __forceinline__ float2 unpackf2(ULL v) {
    unsigned a, b; asm("mov.b64 {%0,%1},%2;" : "=r"(a), "=r"(b) : "l"(v));
    return make_float2(__uint_as_float(a), __uint_as_float(b));
}
__device__ __forceinline__ ULL f2add(ULL a, ULL b) {
    ULL r; asm("add.rn.f32x2 %0,%1,%2;" : "=l"(r) : "l"(a), "l"(b)); return r;
}
__device__ __forceinline__ ULL f2mul(ULL a, ULL b) {
    ULL r; asm("mul.rn.f32x2 %0,%1,%2;" : "=l"(r) : "l"(a), "l"(b)); return r;
}
__device__ __forceinline__ float d2_noFMA(float dx, float dy, float dz) {
    return __fadd_rn(__fadd_rn(__fmul_rn(dx, dx), __fmul_rn(dy, dy)), __fmul_rn(dz, dz));
}

// ---------------- zero stats -------------------------------------------------
__global__ void zero_k() {
    int t = threadIdx.x;
    if (t < 64) { g_s0[t]=0.f; g_q0[t]=0.f; g_s1[t]=0.f; g_q1[t]=0.f; }
    if (t < 128){ g_s2[t]=0.f; g_q2[t]=0.f; }
}

// ---------------- FPS: 1 CTA/batch, 512 thr, 16 pts/thread, 2 barriers ------
__global__ void __launch_bounds__(512) fps_k(const float* __restrict__ xyz) {
    extern __shared__ float sx[];                      // 24576 floats
    __shared__ unsigned swhi[16], swlo[16];
    __shared__ unsigned s_p;
    const int b = blockIdx.x, tid = threadIdx.x, wid = tid >> 5, lane = tid & 31;
    const float* X = xyz + (size_t)b * 24576;

    for (int i = tid; i < 6144; i += 512)
        ((float4*)sx)[i] = ((const float4*)X)[i];
    __syncthreads();

    ULL px[8], py[8], pz[8]; float dist[16];
#pragma unroll
    for (int j = 0; j < 8; j++) {
        int p0 = tid + 1024 * j, p1 = p0 + 512;
        px[j] = packf2(sx[3*p0+0], sx[3*p1+0]);
        py[j] = packf2(sx[3*p0+1], sx[3*p1+1]);
        pz[j] = packf2(sx[3*p0+2], sx[3*p1+2]);
        dist[2*j] = 1e10f; dist[2*j+1] = 1e10f;
    }
    float cx = sx[0], cy = sx[1], cz = sx[2];
    if (tid == 0) g_fpsidx[b * 2048] = 0;

    for (int s = 1; s < 2048; s++) {
        ULL ncx = packf2(-cx, -cx), ncy = packf2(-cy, -cy), ncz = packf2(-cz, -cz);
        float m8 = 0.0f;
#pragma unroll
        for (int j = 0; j < 8; j++) {
            ULL dx = f2add(px[j], ncx);
            ULL dy = f2add(py[j], ncy);
            ULL dz = f2add(pz[j], ncz);
            // mul/add tree, no FMA: matches reference rounding exactly
            ULL d2 = f2add(f2add(f2mul(dx, dx), f2mul(dy, dy)), f2mul(dz, dz));
            float2 d = unpackf2(d2);
            float a = fminf(dist[2*j],   d.x); dist[2*j]   = a;
            float c = fminf(dist[2*j+1], d.y); dist[2*j+1] = c;
            m8 = fmaxf(m8, fmaxf(a, c));
        }
        unsigned mb = __float_as_uint(m8);               // dists >= 0: bit-monotone
        unsigned wm = __reduce_max_sync(0xffffffffu, mb);
        unsigned cand = 0xffffffffu;
        if (mb == wm) {
#pragma unroll
            for (int i = 0; i < 16; i++) {
                if (__float_as_uint(dist[i]) == wm) { cand = (unsigned)(tid + (i << 9)); break; }
            }
        }
        unsigned cmin = __reduce_min_sync(0xffffffffu, cand);
        if (lane == 0) { swhi[wid] = wm; swlo[wid] = cmin; }
        __syncthreads();
        if (wid == 0) {
            unsigned hi = (lane < 16) ? swhi[lane] : 0u;
            unsigned lo = (lane < 16) ? swlo[lane] : 0xffffffffu;
            unsigned hm = __reduce_max_sync(0xffffffffu, hi);
            unsigned lm = __reduce_min_sync(0xffffffffu, (hi == hm) ? lo : 0xffffffffu);
            if (lane == 0) s_p = lm;
        }
        __syncthreads();
        unsigned p = s_p;
        if (tid == 0) g_fpsidx[b * 2048 + s] = (int)p;
        cx = sx[3*p]; cy = sx[3*p+1]; cz = sx[3*p+2];
    }
}

// ---------------- centroids --------------------------------------------------
__global__ void centroid_k(const float* __restrict__ xyz, float* __restrict__ outc) {
    int id = blockIdx.x * 256 + threadIdx.x;
    if (id >= 16384) return;
    int b = id >> 11;
    int p = g_fpsidx[id];
    const float* src = xyz + ((size_t)(b << 13) + p) * 3;
    float x = src[0], y = src[1], z = src[2];
    outc[id*3+0] = x; outc[id*3+1] = y; outc[id*3+2] = z;
    g_cent[id*3+0] = x; g_cent[id*3+1] = y; g_cent[id*3+2] = z;
}

// ---------------- ball query: smem-staged, warp per centroid -----------------
__global__ void __launch_bounds__(512) ballq_k(const float* __restrict__ xyz) {
    extern __shared__ float sb[];                      // 24576 + 512 ints
    int* sidx = (int*)(sb + 24576);
    int tid = threadIdx.x, wid = tid >> 5, lane = tid & 31;
    int cid = blockIdx.x * 16 + wid;                   // 16 centroids / CTA, same batch
    int b = cid >> 11;
    const float* X = xyz + (size_t)b * 24576;
    for (int i = tid; i < 6144; i += 512)
        ((float4*)sb)[i] = ((const float4*)X)[i];
    float cx = g_cent[cid*3], cy = g_cent[cid*3+1], cz = g_cent[cid*3+2];
    __syncthreads();

    int cnt = 0;
    for (int base = 0; base < 8192; base += 32) {
        int j = base + lane;
        float d2 = d2_noFMA(cx - sb[3*j], cy - sb[3*j+1], cz - sb[3*j+2]);
        bool hit = d2 <= 0.04f;
        unsigned m = __ballot_sync(0xffffffffu, hit);
        if (m) {
            int r = __popc(m & ((1u << lane) - 1u));
            if (hit && cnt + r < 32) sidx[wid*32 + cnt + r] = j;
            cnt += __popc(m);
            if (cnt >= 32) break;
        }
    }
    __syncwarp();
    int first = sidx[wid*32];
    int c = cnt < 32 ? cnt : 32;
    g_gidx[cid * 32 + lane] = (lane < c) ? sidx[wid*32 + lane] : first;
}

// ---------------- weight transpose (k-major) ---------------------------------
__global__ void prepw_k(const float* __restrict__ w0, const float* __restrict__ w1,
                        const float* __restrict__ w2) {
    int t = blockIdx.x * 256 + threadIdx.x;
    if (t < 68 * 64) {
        int k = t >> 6, n = t & 63;
        float v = 0.f;
        if (k < 64) v = w0[n * 67 + 3 + k];
        else if (k < 67) v = w0[n * 67 + (k - 64)];
        g_Wt0[k * 64 + n] = v;
    }
    int t1 = t - 68 * 64;
    if (t1 >= 0 && t1 < 64 * 64) {
        int k = t1 >> 6, n = t1 & 63;
        g_Wt1[k * 64 + n] = w1[n * 64 + k];
    }
    int t2 = t1 - 64 * 64;
    if (t2 >= 0 && t2 < 64 * 128) {
        int k = t2 >> 7, n = t2 & 127;
        g_Wt2[k * 128 + n] = w2[n * 64 + k];
    }
}

// ---------------- GEMM: 128-row tile, 256 thr, scalar FMA micro-tile ---------
// MODE 0: A gathered from (feat,xyz,cent,gidx); stats.      KP=68, N=64
// MODE 1: A from Y-prev, fused BN affine + ReLU; stats.     KP=64, N=64
// MODE 2: A fused act; plain store, no stats.               KP=64, N=128
template<int KP, int N, int MODE>
__global__ void __launch_bounds__(256) gemm_k(
    const float* __restrict__ A, const float* __restrict__ Wt,
    const float* __restrict__ bias,
    const float* __restrict__ fa, const float* __restrict__ fc,
    const float* __restrict__ xyz, const float* __restrict__ feat,
    float* __restrict__ Y, float* __restrict__ gs, float* __restrict__ gq)
{
    extern __shared__ float sm[];
    float* As = sm;                  // [128][KP]
    float* Bs = sm + 128 * KP;       // [KP][N]
    float* Ss = Bs + KP * N;         // [2N] stats partials (MODE<2)
    const int tid = threadIdx.x;
    const size_t rb = (size_t)blockIdx.x * 128;

    for (int i = tid; i < KP * N / 4; i += 256)
        ((float4*)Bs)[i] = ((const float4*)Wt)[i];
    if (MODE < 2) for (int i = tid; i < 2 * N; i += 256) Ss[i] = 0.f;

    if (MODE == 0) {
        // gather: 17 float4 chunks per row (16 feat + 1 xyz-norm/pad)
        for (int i = tid; i < 128 * 17; i += 256) {
            int r = i / 17, c4 = i - r * 17;
            int grow = (int)rb + r;
            int j = g_gidx[grow];
            int b = grow >> 16;
            float4 v;
            if (c4 < 16) {
                v = ((const float4*)(feat + ((size_t)(b << 13) + j) * 64))[c4];
            } else {
                const float* xp = xyz + ((size_t)(b << 13) + j) * 3;
                const float* cp = g_cent + (grow >> 5) * 3;
                v = make_float4(xp[0]-cp[0], xp[1]-cp[1], xp[2]-cp[2], 0.f);
            }
            ((float4*)(As + r * KP))[c4] = v;
        }
    } else {
        const int K4 = KP / 4;
        for (int i = tid; i < 128 * K4; i += 256) {
            int r = i / K4, c = i - r * K4;
            float4 v = ((const float4*)(A + (rb + r) * KP))[c];
            int k = c * 4;
            v.x = fmaxf(fmaf(fa[k+0], v.x, fc[k+0]), 0.f);
            v.y = fmaxf(fmaf(fa[k+1], v.y, fc[k+1]), 0.f);
            v.z = fmaxf(fmaf(fa[k+2], v.z, fc[k+2]), 0.f);
            v.w = fmaxf(fmaf(fa[k+3], v.w, fc[k+3]), 0.f);
            ((float4*)(As + r * KP))[c] = v;
        }
    }
    __syncthreads();

    constexpr int NT = N / 16;                        // 4 or 8 cols/thread
    const int tc = (tid & 15) * NT, tr = tid >> 4;
    float acc[8][NT];
#pragma unroll
    for (int i = 0; i < 8; i++)
#pragma unroll
        for (int j = 0; j < NT; j++) acc[i][j] = bias[tc + j];

#pragma unroll 4
    for (int k = 0; k < KP; k++) {
        float av[8];
#pragma unroll
        for (int i = 0; i < 8; i++) av[i] = As[(tr + 16 * i) * KP + k];
        float bv[NT];
#pragma unroll
        for (int j = 0; j < NT; j += 4) {
            float4 t = *(const float4*)&Bs[k * N + tc + j];
            bv[j] = t.x; bv[j+1] = t.y; bv[j+2] = t.z; bv[j+3] = t.w;
        }
#pragma unroll
        for (int i = 0; i < 8; i++)
#pragma unroll
            for (int j = 0; j < NT; j++) acc[i][j] = fmaf(av[i], bv[j], acc[i][j]);
    }

#pragma unroll
    for (int i = 0; i < 8; i++) {
        size_t row = rb + tr + 16 * i;
#pragma unroll
        for (int j = 0; j < NT; j += 4) {
            float4 t = make_float4(acc[i][j], acc[i][j+1], acc[i][j+2], acc[i][j+3]);
            *(float4*)&Y[row * N + tc + j] = t;
        }
    }
    if (MODE < 2) {
#pragma unroll
        for (int j = 0; j < NT; j++) {
            float s = 0.f, q = 0.f;
#pragma unroll
            for (int i = 0; i < 8; i++) { float v = acc[i][j]; s += v; q = fmaf(v, v, q); }
            atomicAdd(&Ss[tc + j], s);
            atomicAdd(&Ss[N + tc + j], q);
        }
        __syncthreads();
        for (int i = tid; i < N; i += 256) {
            atomicAdd(&gs[i], Ss[i]);
            atomicAdd(&gq[i], Ss[N + i]);
        }
    }
}

// ---------------- BN affine finalize -----------------------------------------
__global__ void finalize_k(const float* __restrict__ s, const float* __restrict__ q,
                           const float* __restrict__ g, const float* __restrict__ beta,
                           float* __restrict__ fa, float* __restrict__ fc, int n) {
    int i = blockIdx.x * 64 + threadIdx.x;
    if (i < n) {
        const float inv = 1.0f / 524288.0f;
        float m = s[i] * inv;
        float var = q[i] * inv - m * m;
        float a = g[i] * rsqrtf(var + 1e-5f);
        fa[i] = a;
        fc[i] = fmaf(-m, a, beta[i]);
    }
}

// ---------------- max over K + layer2 stats ----------------------------------
__global__ void __launch_bounds__(128) maxstat_k() {
    int g = blockIdx.x;                               // 0..16383
    int c = threadIdx.x;                              // 0..127
    const float* p = g_y2 + (size_t)g * 32 * 128 + c;
    float m = -3.4e38f, s = 0.f, q = 0.f;
#pragma unroll 4
    for (int r = 0; r < 32; r++) {
        float v = p[(size_t)r * 128];
        m = fmaxf(m, v);
        s += v;
        q = fmaf(v, v, q);
    }
    g_maxraw[g * 128 + c] = m;
    atomicAdd(&g_s2[c], s);
    atomicAdd(&g_q2[c], q);
}

// ---------------- final output ------------------------------------------------
__global__ void out_k(float* __restrict__ out) {
    int id = blockIdx.x * 256 + threadIdx.x;
    int c = id & 127;
    out[id] = fmaxf(fmaf(g_a2[c], g_maxraw[id], g_c2[c]), 0.f);
}

// ---------------- launch ------------------------------------------------------
extern "C" void kernel_launch(void* const* d_in, const int* in_sizes, int n_in,
                              void* d_out, int out_size) {
    const float* xyz  = (const float*)d_in[0];
    const float* feat = (const float*)d_in[1];
    const float* w0 = (const float*)d_in[2],  *b0 = (const float*)d_in[3];
    const float* g0 = (const float*)d_in[4],  *be0 = (const float*)d_in[5];
    const float* w1 = (const float*)d_in[6],  *b1 = (const float*)d_in[7];
    const float* g1 = (const float*)d_in[8],  *be1 = (const float*)d_in[9];
    const float* w2 = (const float*)d_in[10], *b2 = (const float*)d_in[11];
    const float* g2 = (const float*)d_in[12], *be2 = (const float*)d_in[13];
    float* out = (float*)d_out;

    float *ds0,*dq0,*ds1,*dq1,*ds2,*dq2,*da0,*dc0,*da1,*dc1,*da2,*dc2;
    cudaGetSymbolAddress((void**)&ds0, g_s0); cudaGetSymbolAddress((void**)&dq0, g_q0);
    cudaGetSymbolAddress((void**)&ds1, g_s1); cudaGetSymbolAddress((void**)&dq1, g_q1);
    cudaGetSymbolAddress((void**)&ds2, g_s2); cudaGetSymbolAddress((void**)&dq2, g_q2);
    cudaGetSymbolAddress((void**)&da0, g_a0); cudaGetSymbolAddress((void**)&dc0, g_c0);
    cudaGetSymbolAddress((void**)&da1, g_a1); cudaGetSymbolAddress((void**)&dc1, g_c1);
    cudaGetSymbolAddress((void**)&da2, g_a2); cudaGetSymbolAddress((void**)&dc2, g_c2);
    float *dy0,*dy1,*dy2,*dWt0,*dWt1,*dWt2;
    cudaGetSymbolAddress((void**)&dy0, g_y0);
    cudaGetSymbolAddress((void**)&dy1, g_y1);
    cudaGetSymbolAddress((void**)&dy2, g_y2);
    cudaGetSymbolAddress((void**)&dWt0, g_Wt0);
    cudaGetSymbolAddress((void**)&dWt1, g_Wt1);
    cudaGetSymbolAddress((void**)&dWt2, g_Wt2);

    const int smemF = 24576 * 4;                     // fps
    const int smemB = 24576 * 4 + 512 * 4;           // ballq
    const int smem0 = (128*68 + 68*64 + 128) * 4;    // 52736
    const int smem1 = (128*64 + 64*64 + 128) * 4;    // 49664
    const int smem2 = (128*64 + 64*128) * 4;         // 65536
    cudaFuncSetAttribute(fps_k,   cudaFuncAttributeMaxDynamicSharedMemorySize, smemF);
    cudaFuncSetAttribute(ballq_k, cudaFuncAttributeMaxDynamicSharedMemorySize, smemB);
    cudaFuncSetAttribute(gemm_k<68,64,0>,  cudaFuncAttributeMaxDynamicSharedMemorySize, smem0);
    cudaFuncSetAttribute(gemm_k<64,64,1>,  cudaFuncAttributeMaxDynamicSharedMemorySize, smem1);
    cudaFuncSetAttribute(gemm_k<64,128,2>, cudaFuncAttributeMaxDynamicSharedMemorySize, smem2);

    zero_k<<<1, 128>>>();
    fps_k<<<8, 512, smemF>>>(xyz);
    centroid_k<<<64, 256>>>(xyz, out);               // out[0..49151] = centroids
    ballq_k<<<1024, 512, smemB>>>(xyz);
    prepw_k<<<65, 256>>>(w0, w1, w2);
    gemm_k<68,64,0><<<4096, 256, smem0>>>(nullptr, dWt0, b0, nullptr, nullptr,
                                          xyz, feat, dy0, ds0, dq0);
    finalize_k<<<1, 64>>>(ds0, dq0, g0, be0, da0, dc0, 64);
    gemm_k<64,64,1><<<4096, 256, smem1>>>(dy0, dWt1, b1, da0, dc0,
                                          nullptr, nullptr, dy1, ds1, dq1);
    finalize_k<<<1, 64>>>(ds1, dq1, g1, be1, da1, dc1, 64);
    gemm_k<64,128,2><<<4096, 256, smem2>>>(dy1, dWt2, b2, da1, dc1,
                                           nullptr, nullptr, dy2, nullptr, nullptr);
    maxstat_k<<<16384, 128>>>();
    finalize_k<<<2, 64>>>(ds2, dq2, g2, be2, da2, dc2, 128);
    out_k<<<8192, 256>>>(out + 49152);
}

// round 8
// speedup vs baseline: 1.3980x; 1.2667x over previous
#include <cuda_runtime.h>
#include <cuda_bf16.h>
#include <cstdint>

typedef unsigned long long ULL;

// ---------------- scratch (static device globals; no allocation) ------------
__device__ float g_y0[524288 * 64];
__device__ float g_y1[524288 * 64];
__device__ float g_maxraw[16384 * 128];
__device__ int   g_fpsidx[16384];
__device__ float g_cent[16384 * 3];
__device__ int   g_gidx[524288];
__device__ float g_Wt0[68 * 64];
__device__ float g_Wt1[64 * 64];
__device__ float g_Wt2[64 * 128];
__device__ float g_s0[64], g_q0[64], g_s1[64], g_q1[64], g_s2[128], g_q2[128];
__device__ float g_a0[64], g_c0[64], g_a1[64], g_c1[64], g_a2[128], g_c2[128];

// ---------------- helpers ---------------------------------------------------
__device__ __forceinline__ ULL packf2(float lo, float hi) {
    ULL r; unsigned a = __float_as_uint(lo), b = __float_as_uint(hi);
    asm("mov.b64 %0,{%1,%2};" : "=l"(r) : "r"(a), "r"(b)); return r;
}
__device__ __forceinline__ float2 unpackf2(ULL v) {
    unsigned a, b; asm("mov.b64 {%0,%1},%2;" : "=r"(a), "=r"(b) : "l"(v));
    return make_float2(__uint_as_float(a), __uint_as_float(b));
}
__device__ __forceinline__ ULL f2add(ULL a, ULL b) {
    ULL r; asm("add.rn.f32x2 %0,%1,%2;" : "=l"(r) : "l"(a), "l"(b)); return r;
}
__device__ __forceinline__ ULL f2mul(ULL a, ULL b) {
    ULL r; asm("mul.rn.f32x2 %0,%1,%2;" : "=l"(r) : "l"(a), "l"(b)); return r;
}
__device__ __forceinline__ float d2_noFMA(float dx, float dy, float dz) {
    return __fadd_rn(__fadd_rn(__fmul_rn(dx, dx), __fmul_rn(dy, dy)), __fmul_rn(dz, dz));
}

// ---------------- zero stats -------------------------------------------------
__global__ void zero_k() {
    int t = threadIdx.x;
    if (t < 64) { g_s0[t]=0.f; g_q0[t]=0.f; g_s1[t]=0.f; g_q1[t]=0.f; }
    if (t < 128){ g_s2[t]=0.f; g_q2[t]=0.f; }
}

// ---------------- FPS: 1 CTA/batch, 1024 thr, 8 pts/thread, 2 barriers ------
__global__ void __launch_bounds__(1024) fps_k(const float* __restrict__ xyz) {
    extern __shared__ float sx[];                      // 24576 floats
    __shared__ unsigned swhi[32], swlo[32];
    __shared__ unsigned s_p;
    const int b = blockIdx.x, tid = threadIdx.x, wid = tid >> 5, lane = tid & 31;
    const float* X = xyz + (size_t)b * 24576;

    for (int i = tid; i < 6144; i += 1024)
        ((float4*)sx)[i] = ((const float4*)X)[i];
    __syncthreads();

    ULL px[4], py[4], pz[4]; float dist[8];
#pragma unroll
    for (int j = 0; j < 4; j++) {
        int p0 = tid + 2048 * j, p1 = p0 + 1024;
        px[j] = packf2(sx[3*p0+0], sx[3*p1+0]);
        py[j] = packf2(sx[3*p0+1], sx[3*p1+1]);
        pz[j] = packf2(sx[3*p0+2], sx[3*p1+2]);
        dist[2*j] = 1e10f; dist[2*j+1] = 1e10f;
    }
    float cx = sx[0], cy = sx[1], cz = sx[2];
    if (tid == 0) g_fpsidx[b * 2048] = 0;

    for (int s = 1; s < 2048; s++) {
        ULL ncx = packf2(-cx, -cx), ncy = packf2(-cy, -cy), ncz = packf2(-cz, -cz);
        float m8 = 0.0f;
#pragma unroll
        for (int j = 0; j < 4; j++) {
            ULL dx = f2add(px[j], ncx);
            ULL dy = f2add(py[j], ncy);
            ULL dz = f2add(pz[j], ncz);
            // mul/add tree, no FMA: matches reference rounding exactly
            ULL d2 = f2add(f2add(f2mul(dx, dx), f2mul(dy, dy)), f2mul(dz, dz));
            float2 d = unpackf2(d2);
            float a = fminf(dist[2*j],   d.x); dist[2*j]   = a;
            float c = fminf(dist[2*j+1], d.y); dist[2*j+1] = c;
            m8 = fmaxf(m8, fmaxf(a, c));
        }
        unsigned mb = __float_as_uint(m8);               // dists >= 0: bit-monotone
        unsigned wm = __reduce_max_sync(0xffffffffu, mb);
        unsigned cand = 0xffffffffu;
        if (mb == wm) {
#pragma unroll
            for (int i = 0; i < 8; i++) {
                if (__float_as_uint(dist[i]) == wm) { cand = (unsigned)(tid + (i << 10)); break; }
            }
        }
        unsigned cmin = __reduce_min_sync(0xffffffffu, cand);
        if (lane == 0) { swhi[wid] = wm; swlo[wid] = cmin; }
        __syncthreads();
        if (wid == 0) {
            unsigned hi = swhi[lane];
            unsigned lo = swlo[lane];
            unsigned hm = __reduce_max_sync(0xffffffffu, hi);
            unsigned lm = __reduce_min_sync(0xffffffffu, (hi == hm) ? lo : 0xffffffffu);
            if (lane == 0) s_p = lm;
        }
        __syncthreads();
        unsigned p = s_p;
        if (tid == 0) g_fpsidx[b * 2048 + s] = (int)p;
        cx = sx[3*p]; cy = sx[3*p+1]; cz = sx[3*p+2];
    }
}

// ---------------- centroids --------------------------------------------------
__global__ void centroid_k(const float* __restrict__ xyz, float* __restrict__ outc) {
    int id = blockIdx.x * 256 + threadIdx.x;
    if (id >= 16384) return;
    int b = id >> 11;
    int p = g_fpsidx[id];
    const float* src = xyz + ((size_t)(b << 13) + p) * 3;
    float x = src[0], y = src[1], z = src[2];
    outc[id*3+0] = x; outc[id*3+1] = y; outc[id*3+2] = z;
    g_cent[id*3+0] = x; g_cent[id*3+1] = y; g_cent[id*3+2] = z;
}

// ---------------- ball query: smem-staged, warp per centroid -----------------
__global__ void __launch_bounds__(512) ballq_k(const float* __restrict__ xyz) {
    extern __shared__ float sb[];                      // 24576 + 512 ints
    int* sidx = (int*)(sb + 24576);
    int tid = threadIdx.x, wid = tid >> 5, lane = tid & 31;
    int cid = blockIdx.x * 16 + wid;                   // 16 centroids / CTA, same batch
    int b = cid >> 11;
    const float* X = xyz + (size_t)b * 24576;
    for (int i = tid; i < 6144; i += 512)
        ((float4*)sb)[i] = ((const float4*)X)[i];
    float cx = g_cent[cid*3], cy = g_cent[cid*3+1], cz = g_cent[cid*3+2];
    __syncthreads();

    int cnt = 0;
    for (int base = 0; base < 8192; base += 32) {
        int j = base + lane;
        float d2 = d2_noFMA(cx - sb[3*j], cy - sb[3*j+1], cz - sb[3*j+2]);
        bool hit = d2 <= 0.04f;
        unsigned m = __ballot_sync(0xffffffffu, hit);
        if (m) {
            int r = __popc(m & ((1u << lane) - 1u));
            if (hit && cnt + r < 32) sidx[wid*32 + cnt + r] = j;
            cnt += __popc(m);
            if (cnt >= 32) break;
        }
    }
    __syncwarp();
    int first = sidx[wid*32];
    int c = cnt < 32 ? cnt : 32;
    g_gidx[cid * 32 + lane] = (lane < c) ? sidx[wid*32 + lane] : first;
}

// ---------------- weight transpose (k-major) ---------------------------------
__global__ void prepw_k(const float* __restrict__ w0, const float* __restrict__ w1,
                        const float* __restrict__ w2) {
    int t = blockIdx.x * 256 + threadIdx.x;
    if (t < 68 * 64) {
        int k = t >> 6, n = t & 63;
        float v = 0.f;
        if (k < 64) v = w0[n * 67 + 3 + k];
        else if (k < 67) v = w0[n * 67 + (k - 64)];
        g_Wt0[k * 64 + n] = v;
    }
    int t1 = t - 68 * 64;
    if (t1 >= 0 && t1 < 64 * 64) {
        int k = t1 >> 6, n = t1 & 63;
        g_Wt1[k * 64 + n] = w1[n * 64 + k];
    }
    int t2 = t1 - 64 * 64;
    if (t2 >= 0 && t2 < 64 * 128) {
        int k = t2 >> 7, n = t2 & 127;
        g_Wt2[k * 128 + n] = w2[n * 64 + k];
    }
}

// ---------------- GEMM 0/1: 128-row tile, 256 thr, scalar FMA ----------------
// MODE 0: A gathered from (feat,xyz,cent,gidx); stats.      KP=68, N=64
// MODE 1: A from Y-prev, fused BN affine + ReLU; stats.     KP=64, N=64
template<int KP, int N, int MODE>
__global__ void __launch_bounds__(256) gemm_k(
    const float* __restrict__ A, const float* __restrict__ Wt,
    const float* __restrict__ bias,
    const float* __restrict__ fa, const float* __restrict__ fc,
    const float* __restrict__ xyz, const float* __restrict__ feat,
    float* __restrict__ Y, float* __restrict__ gs, float* __restrict__ gq)
{
    extern __shared__ float sm[];
    float* As = sm;                  // [128][KP]
    float* Bs = sm + 128 * KP;       // [KP][N]
    float* Ss = Bs + KP * N;         // [2N] stats partials
    const int tid = threadIdx.x;
    const size_t rb = (size_t)blockIdx.x * 128;

    for (int i = tid; i < KP * N / 4; i += 256)
        ((float4*)Bs)[i] = ((const float4*)Wt)[i];
    for (int i = tid; i < 2 * N; i += 256) Ss[i] = 0.f;

    if (MODE == 0) {
        for (int i = tid; i < 128 * 17; i += 256) {
            int r = i / 17, c4 = i - r * 17;
            int grow = (int)rb + r;
            int j = g_gidx[grow];
            int b = grow >> 16;
            float4 v;
            if (c4 < 16) {
                v = ((const float4*)(feat + ((size_t)(b << 13) + j) * 64))[c4];
            } else {
                const float* xp = xyz + ((size_t)(b << 13) + j) * 3;
                const float* cp = g_cent + (grow >> 5) * 3;
                v = make_float4(xp[0]-cp[0], xp[1]-cp[1], xp[2]-cp[2], 0.f);
            }
            ((float4*)(As + r * KP))[c4] = v;
        }
    } else {
        const int K4 = KP / 4;
        for (int i = tid; i < 128 * K4; i += 256) {
            int r = i / K4, c = i - r * K4;
            float4 v = ((const float4*)(A + (rb + r) * KP))[c];
            int k = c * 4;
            v.x = fmaxf(fmaf(fa[k+0], v.x, fc[k+0]), 0.f);
            v.y = fmaxf(fmaf(fa[k+1], v.y, fc[k+1]), 0.f);
            v.z = fmaxf(fmaf(fa[k+2], v.z, fc[k+2]), 0.f);
            v.w = fmaxf(fmaf(fa[k+3], v.w, fc[k+3]), 0.f);
            ((float4*)(As + r * KP))[c] = v;
        }
    }
    __syncthreads();

    constexpr int NT = N / 16;                        // 4 cols/thread
    const int tc = (tid & 15) * NT, tr = tid >> 4;
    float acc[8][NT];
#pragma unroll
    for (int i = 0; i < 8; i++)
#pragma unroll
        for (int j = 0; j < NT; j++) acc[i][j] = bias[tc + j];

#pragma unroll 4
    for (int k = 0; k < KP; k++) {
        float av[8];
#pragma unroll
        for (int i = 0; i < 8; i++) av[i] = As[(tr + 16 * i) * KP + k];
        float bv[NT];
#pragma unroll
        for (int j = 0; j < NT; j += 4) {
            float4 t = *(const float4*)&Bs[k * N + tc + j];
            bv[j] = t.x; bv[j+1] = t.y; bv[j+2] = t.z; bv[j+3] = t.w;
        }
#pragma unroll
        for (int i = 0; i < 8; i++)
#pragma unroll
            for (int j = 0; j < NT; j++) acc[i][j] = fmaf(av[i], bv[j], acc[i][j]);
    }

#pragma unroll
    for (int i = 0; i < 8; i++) {
        size_t row = rb + tr + 16 * i;
#pragma unroll
        for (int j = 0; j < NT; j += 4) {
            float4 t = make_float4(acc[i][j], acc[i][j+1], acc[i][j+2], acc[i][j+3]);
            *(float4*)&Y[row * N + tc + j] = t;
        }
    }
#pragma unroll
    for (int j = 0; j < NT; j++) {
        float s = 0.f, q = 0.f;
#pragma unroll
        for (int i = 0; i < 8; i++) { float v = acc[i][j]; s += v; q = fmaf(v, v, q); }
        atomicAdd(&Ss[tc + j], s);
        atomicAdd(&Ss[N + tc + j], q);
    }
    __syncthreads();
    for (int i = tid; i < N; i += 256) {
        atomicAdd(&gs[i], Ss[i]);
        atomicAdd(&gq[i], Ss[N + i]);
    }
}

// ---------------- GEMM 2: 128x128 tile, fused max-over-K + stats -------------
// A (y1) with fused BN affine + ReLU, W [64][128]. No Y store: epilogue computes
// per-32-row-group max (each 32-row group = one centroid's K neighbors) + stats.
// Thread: rows tr+32m (m=0..3, one per group), cols (tid&7)*4 + j + 32*c.
__global__ void __launch_bounds__(256) gemm2_k(
    const float* __restrict__ A, const float* __restrict__ Wt,
    const float* __restrict__ bias,
    const float* __restrict__ fa, const float* __restrict__ fc,
    float* __restrict__ gs, float* __restrict__ gq)
{
    extern __shared__ float sm[];
    float* As   = sm;                    // [128][65] padded
    float* Bs   = sm + 128 * 65;         // [64][128]
    float* smax = Bs + 64 * 128;         // [8*4][128]
    float* ssum = smax + 8 * 4 * 128;    // [8][128]
    float* ssq  = ssum + 8 * 128;        // [8][128]
    const int tid = threadIdx.x;
    const size_t rb = (size_t)blockIdx.x * 128;

    for (int i = tid; i < 64 * 128 / 4; i += 256)
        ((float4*)Bs)[i] = ((const float4*)Wt)[i];

    // stage A: affine+relu, transposed-padded store (stride 65, conflict-free reads)
    for (int i = tid; i < 128 * 16; i += 256) {
        int r = i >> 4, c = i & 15;
        float4 v = ((const float4*)(A + (rb + r) * 64))[c];
        int k = c * 4;
        v.x = fmaxf(fmaf(fa[k+0], v.x, fc[k+0]), 0.f);
        v.y = fmaxf(fmaf(fa[k+1], v.y, fc[k+1]), 0.f);
        v.z = fmaxf(fmaf(fa[k+2], v.z, fc[k+2]), 0.f);
        v.w = fmaxf(fmaf(fa[k+3], v.w, fc[k+3]), 0.f);
        float* p = As + r * 65 + k;
        p[0] = v.x; p[1] = v.y; p[2] = v.z; p[3] = v.w;
    }
    __syncthreads();

    const int tc8 = (tid & 7) * 4;       // base col within each 32-chunk
    const int tr  = tid >> 3;            // 0..31
    float acc[4][16];
#pragma unroll
    for (int c = 0; c < 4; c++)
#pragma unroll
        for (int j = 0; j < 4; j++) {
            float bb = bias[tc8 + j + 32 * c];
#pragma unroll
            for (int m = 0; m < 4; m++) acc[m][c*4+j] = bb;
        }

#pragma unroll 4
    for (int k = 0; k < 64; k++) {
        float av[4];
#pragma unroll
        for (int m = 0; m < 4; m++) av[m] = As[(tr + 32*m) * 65 + k];
        float bv[16];
#pragma unroll
        for (int c = 0; c < 4; c++) {
            float4 t = *(const float4*)&Bs[k * 128 + tc8 + 32 * c];
            bv[c*4+0] = t.x; bv[c*4+1] = t.y; bv[c*4+2] = t.z; bv[c*4+3] = t.w;
        }
#pragma unroll
        for (int m = 0; m < 4; m++)
#pragma unroll
            for (int j = 0; j < 16; j++) acc[m][j] = fmaf(av[m], bv[j], acc[m][j]);
    }

    // epilogue: per-col stats (sum over 4 rows) + per-group max; reduce over tr.
    float s[16], q[16];
#pragma unroll
    for (int j = 0; j < 16; j++) {
        s[j] = acc[0][j] + acc[1][j] + acc[2][j] + acc[3][j];
        q[j] = fmaf(acc[0][j], acc[0][j], fmaf(acc[1][j], acc[1][j],
               fmaf(acc[2][j], acc[2][j], acc[3][j] * acc[3][j])));
    }
    // warp holds tr = 4w..4w+3 at lane strides of 8: shfl-xor 8,16 reduces over tr
#pragma unroll
    for (int j = 0; j < 16; j++) {
#pragma unroll
        for (int m = 0; m < 4; m++) {
            acc[m][j] = fmaxf(acc[m][j], __shfl_xor_sync(0xffffffffu, acc[m][j], 8));
            acc[m][j] = fmaxf(acc[m][j], __shfl_xor_sync(0xffffffffu, acc[m][j], 16));
        }
        s[j] += __shfl_xor_sync(0xffffffffu, s[j], 8);
        s[j] += __shfl_xor_sync(0xffffffffu, s[j], 16);
        q[j] += __shfl_xor_sync(0xffffffffu, q[j], 8);
        q[j] += __shfl_xor_sync(0xffffffffu, q[j], 16);
    }
    int w = tid >> 5, lane = tid & 31;
    if (lane < 8) {
#pragma unroll
        for (int c = 0; c < 4; c++)
#pragma unroll
            for (int j = 0; j < 4; j++) {
                int col = lane * 4 + j + 32 * c;
#pragma unroll
                for (int m = 0; m < 4; m++) smax[(w*4 + m) * 128 + col] = acc[m][c*4+j];
                ssum[w * 128 + col] = s[c*4+j];
                ssq[w * 128 + col]  = q[c*4+j];
            }
    }
    __syncthreads();
    for (int cell = tid; cell < 512; cell += 256) {
        int m = cell >> 7, col = cell & 127;
        float v = smax[m * 128 + col];
#pragma unroll
        for (int ww = 1; ww < 8; ww++) v = fmaxf(v, smax[(ww*4 + m) * 128 + col]);
        g_maxraw[((size_t)blockIdx.x * 4 + m) * 128 + col] = v;
    }
    if (tid < 128) {
        float ss = 0.f, qq = 0.f;
#pragma unroll
        for (int ww = 0; ww < 8; ww++) { ss += ssum[ww*128 + tid]; qq += ssq[ww*128 + tid]; }
        atomicAdd(&gs[tid], ss);
        atomicAdd(&gq[tid], qq);
    }
}

// ---------------- BN affine finalize -----------------------------------------
__global__ void finalize_k(const float* __restrict__ s, const float* __restrict__ q,
                           const float* __restrict__ g, const float* __restrict__ beta,
                           float* __restrict__ fa, float* __restrict__ fc, int n) {
    int i = blockIdx.x * 64 + threadIdx.x;
    if (i < n) {
        const float inv = 1.0f / 524288.0f;
        float m = s[i] * inv;
        float var = q[i] * inv - m * m;
        float a = g[i] * rsqrtf(var + 1e-5f);
        fa[i] = a;
        fc[i] = fmaf(-m, a, beta[i]);
    }
}

// ---------------- final output ------------------------------------------------
__global__ void out_k(float* __restrict__ out) {
    int id = blockIdx.x * 256 + threadIdx.x;
    int c = id & 127;
    out[id] = fmaxf(fmaf(g_a2[c], g_maxraw[id], g_c2[c]), 0.f);
}

// ---------------- launch ------------------------------------------------------
extern "C" void kernel_launch(void* const* d_in, const int* in_sizes, int n_in,
                              void* d_out, int out_size) {
    const float* xyz  = (const float*)d_in[0];
    const float* feat = (const float*)d_in[1];
    const float* w0 = (const float*)d_in[2],  *b0 = (const float*)d_in[3];
    const float* g0 = (const float*)d_in[4],  *be0 = (const float*)d_in[5];
    const float* w1 = (const float*)d_in[6],  *b1 = (const float*)d_in[7];
    const float* g1 = (const float*)d_in[8],  *be1 = (const float*)d_in[9];
    const float* w2 = (const float*)d_in[10], *b2 = (const float*)d_in[11];
    const float* g2 = (const float*)d_in[12], *be2 = (const float*)d_in[13];
    float* out = (float*)d_out;

    float *ds0,*dq0,*ds1,*dq1,*ds2,*dq2,*da0,*dc0,*da1,*dc1,*da2,*dc2;
    cudaGetSymbolAddress((void**)&ds0, g_s0); cudaGetSymbolAddress((void**)&dq0, g_q0);
    cudaGetSymbolAddress((void**)&ds1, g_s1); cudaGetSymbolAddress((void**)&dq1, g_q1);
    cudaGetSymbolAddress((void**)&ds2, g_s2); cudaGetSymbolAddress((void**)&dq2, g_q2);
    cudaGetSymbolAddress((void**)&da0, g_a0); cudaGetSymbolAddress((void**)&dc0, g_c0);
    cudaGetSymbolAddress((void**)&da1, g_a1); cudaGetSymbolAddress((void**)&dc1, g_c1);
    cudaGetSymbolAddress((void**)&da2, g_a2); cudaGetSymbolAddress((void**)&dc2, g_c2);
    float *dy0,*dy1,*dWt0,*dWt1,*dWt2;
    cudaGetSymbolAddress((void**)&dy0, g_y0);
    cudaGetSymbolAddress((void**)&dy1, g_y1);
    cudaGetSymbolAddress((void**)&dWt0, g_Wt0);
    cudaGetSymbolAddress((void**)&dWt1, g_Wt1);
    cudaGetSymbolAddress((void**)&dWt2, g_Wt2);

    const int smemF = 24576 * 4;                     // fps
    const int smemB = 24576 * 4 + 512 * 4;           // ballq
    const int smem0 = (128*68 + 68*64 + 128) * 4;    // 52736
    const int smem1 = (128*64 + 64*64 + 128) * 4;    // 49664
    const int smem2 = (128*65 + 64*128 + 8*4*128 + 2*8*128) * 4; // 90624
    cudaFuncSetAttribute(fps_k,   cudaFuncAttributeMaxDynamicSharedMemorySize, smemF);
    cudaFuncSetAttribute(ballq_k, cudaFuncAttributeMaxDynamicSharedMemorySize, smemB);
    cudaFuncSetAttribute(gemm_k<68,64,0>, cudaFuncAttributeMaxDynamicSharedMemorySize, smem0);
    cudaFuncSetAttribute(gemm_k<64,64,1>, cudaFuncAttributeMaxDynamicSharedMemorySize, smem1);
    cudaFuncSetAttribute(gemm2_k,         cudaFuncAttributeMaxDynamicSharedMemorySize, smem2);

    zero_k<<<1, 128>>>();
    fps_k<<<8, 1024, smemF>>>(xyz);
    centroid_k<<<64, 256>>>(xyz, out);               // out[0..49151] = centroids
    ballq_k<<<1024, 512, smemB>>>(xyz);
    prepw_k<<<65, 256>>>(w0, w1, w2);
    gemm_k<68,64,0><<<4096, 256, smem0>>>(nullptr, dWt0, b0, nullptr, nullptr,
                                          xyz, feat, dy0, ds0, dq0);
    finalize_k<<<1, 64>>>(ds0, dq0, g0, be0, da0, dc0, 64);
    gemm_k<64,64,1><<<4096, 256, smem1>>>(dy0, dWt1, b1, da0, dc0,
                                          nullptr, nullptr, dy1, ds1, dq1);
    finalize_k<<<1, 64>>>(ds1, dq1, g1, be1, da1, dc1, 64);
    gemm2_k<<<4096, 256, smem2>>>(dy1, dWt2, b2, da1, dc1, ds2, dq2);
    finalize_k<<<2, 64>>>(ds2, dq2, g2, be2, da2, dc2, 128);
    out_k<<<8192, 256>>>(out + 49152);
}

// round 10
// speedup vs baseline: 1.4217x; 1.0170x over previous
#include <cuda_runtime.h>
#include <cuda_bf16.h>
#include <cstdint>

typedef unsigned long long ULL;

// ---------------- scratch (static device globals; no allocation) ------------
__device__ float g_y0[524288 * 64];
__device__ float g_y1[524288 * 64];
__device__ float g_maxraw[16384 * 128];
__device__ int   g_fpsidx[16384];
__device__ float g_cent[16384 * 3];
__device__ int   g_gidx[524288];
__device__ float g_Wt0[68 * 64];
__device__ float g_Wt1[64 * 64];
__device__ float g_Wt2[64 * 128];
__device__ float g_s0[64], g_q0[64], g_s1[64], g_q1[64], g_s2[128], g_q2[128];
__device__ float g_a0[64], g_c0[64], g_a1[64], g_c1[64], g_a2[128], g_c2[128];

// ---------------- helpers ---------------------------------------------------
__device__ __forceinline__ ULL packf2(float lo, float hi) {
    ULL r; unsigned a = __float_as_uint(lo), b = __float_as_uint(hi);
    asm("mov.b64 %0,{%1,%2};" : "=l"(r) : "r"(a), "r"(b)); return r;
}
__device__ __forceinline__ float2 unpackf2(ULL v) {
    unsigned a, b; asm("mov.b64 {%0,%1},%2;" : "=r"(a), "=r"(b) : "l"(v));
    return make_float2(__uint_as_float(a), __uint_as_float(b));
}
__device__ __forceinline__ ULL f2add(ULL a, ULL b) {
    ULL r; asm("add.rn.f32x2 %0,%1,%2;" : "=l"(r) : "l"(a), "l"(b)); return r;
}
__device__ __forceinline__ ULL f2mul(ULL a, ULL b) {
    ULL r; asm("mul.rn.f32x2 %0,%1,%2;" : "=l"(r) : "l"(a), "l"(b)); return r;
}
__device__ __forceinline__ float d2_noFMA(float dx, float dy, float dz) {
    return __fadd_rn(__fadd_rn(__fmul_rn(dx, dx), __fmul_rn(dy, dy)), __fmul_rn(dz, dz));
}

// ---------------- zero stats -------------------------------------------------
__global__ void zero_k() {
    int t = threadIdx.x;
    if (t < 64) { g_s0[t]=0.f; g_q0[t]=0.f; g_s1[t]=0.f; g_q1[t]=0.f; }
    if (t < 128){ g_s2[t]=0.f; g_q2[t]=0.f; }
}

// ---------------- FPS: 1 CTA/batch, 1024 thr, 8 pts/thread, 1 barrier -------
__global__ void __launch_bounds__(1024) fps_k(const float* __restrict__ xyz) {
    extern __shared__ float sx[];                      // 24576 floats
    __shared__ unsigned swhi[2][32], swlo[2][32];
    const int b = blockIdx.x, tid = threadIdx.x, wid = tid >> 5, lane = tid & 31;
    const float* X = xyz + (size_t)b * 24576;

    for (int i = tid; i < 6144; i += 1024)
        ((float4*)sx)[i] = ((const float4*)X)[i];
    __syncthreads();

    ULL px[4], py[4], pz[4]; float dist[8];
#pragma unroll
    for (int j = 0; j < 4; j++) {
        int p0 = tid + 2048 * j, p1 = p0 + 1024;
        px[j] = packf2(sx[3*p0+0], sx[3*p1+0]);
        py[j] = packf2(sx[3*p0+1], sx[3*p1+1]);
        pz[j] = packf2(sx[3*p0+2], sx[3*p1+2]);
        dist[2*j] = 1e10f; dist[2*j+1] = 1e10f;
    }
    float cx = sx[0], cy = sx[1], cz = sx[2];
    if (tid == 0) g_fpsidx[b * 2048] = 0;

    for (int s = 1; s < 2048; s++) {
        const int pb = s & 1;
        ULL ncx = packf2(-cx, -cx), ncy = packf2(-cy, -cy), ncz = packf2(-cz, -cz);
        float m8 = 0.0f;
#pragma unroll
        for (int j = 0; j < 4; j++) {
            ULL dx = f2add(px[j], ncx);
            ULL dy = f2add(py[j], ncy);
            ULL dz = f2add(pz[j], ncz);
            // mul/add tree, no FMA: matches reference rounding exactly
            ULL d2 = f2add(f2add(f2mul(dx, dx), f2mul(dy, dy)), f2mul(dz, dz));
            float2 d = unpackf2(d2);
            float a = fminf(dist[2*j],   d.x); dist[2*j]   = a;
            float c = fminf(dist[2*j+1], d.y); dist[2*j+1] = c;
            m8 = fmaxf(m8, fmaxf(a, c));
        }
        unsigned mb = __float_as_uint(m8);               // dists >= 0: bit-monotone
        unsigned wm = __reduce_max_sync(0xffffffffu, mb);
        unsigned cand = 0xffffffffu;                     // cand == point index
        if (mb == wm) {
#pragma unroll
            for (int i = 0; i < 8; i++) {
                if (__float_as_uint(dist[i]) == wm) { cand = (unsigned)(tid + (i << 10)); break; }
            }
        }
        unsigned cmin = __reduce_min_sync(0xffffffffu, cand);
        if (lane == 0) { swhi[pb][wid] = wm; swlo[pb][wid] = cmin; }
        __syncthreads();
        // every warp redundantly reduces the 32 partials -> no second barrier
        unsigned hi = swhi[pb][lane];
        unsigned lo = swlo[pb][lane];
        unsigned hm = __reduce_max_sync(0xffffffffu, hi);
        unsigned p  = __reduce_min_sync(0xffffffffu, (hi == hm) ? lo : 0xffffffffu);
        if (tid == 0) g_fpsidx[b * 2048 + s] = (int)p;
        cx = sx[3*p]; cy = sx[3*p+1]; cz = sx[3*p+2];
    }
}

// ---------------- centroids --------------------------------------------------
__global__ void centroid_k(const float* __restrict__ xyz, float* __restrict__ outc) {
    int id = blockIdx.x * 256 + threadIdx.x;
    if (id >= 16384) return;
    int b = id >> 11;
    int p = g_fpsidx[id];
    const float* src = xyz + ((size_t)(b << 13) + p) * 3;
    float x = src[0], y = src[1], z = src[2];
    outc[id*3+0] = x; outc[id*3+1] = y; outc[id*3+2] = z;
    g_cent[id*3+0] = x; g_cent[id*3+1] = y; g_cent[id*3+2] = z;
}

// ---------------- ball query: smem-staged, warp per centroid -----------------
__global__ void __launch_bounds__(512) ballq_k(const float* __restrict__ xyz) {
    extern __shared__ float sb[];                      // 24576 + 512 ints
    int* sidx = (int*)(sb + 24576);
    int tid = threadIdx.x, wid = tid >> 5, lane = tid & 31;
    int cid = blockIdx.x * 16 + wid;                   // 16 centroids / CTA, same batch
    int b = cid >> 11;
    const float* X = xyz + (size_t)b * 24576;
    for (int i = tid; i < 6144; i += 512)
        ((float4*)sb)[i] = ((const float4*)X)[i];
    float cx = g_cent[cid*3], cy = g_cent[cid*3+1], cz = g_cent[cid*3+2];
    __syncthreads();

    int cnt = 0;
    for (int base = 0; base < 8192; base += 32) {
        int j = base + lane;
        float d2 = d2_noFMA(cx - sb[3*j], cy - sb[3*j+1], cz - sb[3*j+2]);
        bool hit = d2 <= 0.04f;
        unsigned m = __ballot_sync(0xffffffffu, hit);
        if (m) {
            int r = __popc(m & ((1u << lane) - 1u));
            if (hit && cnt + r < 32) sidx[wid*32 + cnt + r] = j;
            cnt += __popc(m);
            if (cnt >= 32) break;
        }
    }
    __syncwarp();
    int first = sidx[wid*32];
    int c = cnt < 32 ? cnt : 32;
    g_gidx[cid * 32 + lane] = (lane < c) ? sidx[wid*32 + lane] : first;
}

// ---------------- weight transpose (k-major) ---------------------------------
__global__ void prepw_k(const float* __restrict__ w0, const float* __restrict__ w1,
                        const float* __restrict__ w2) {
    int t = blockIdx.x * 256 + threadIdx.x;
    if (t < 68 * 64) {
        int k = t >> 6, n = t & 63;
        float v = 0.f;
        if (k < 64) v = w0[n * 67 + 3 + k];
        else if (k < 67) v = w0[n * 67 + (k - 64)];
        g_Wt0[k * 64 + n] = v;
    }
    int t1 = t - 68 * 64;
    if (t1 >= 0 && t1 < 64 * 64) {
        int k = t1 >> 6, n = t1 & 63;
        g_Wt1[k * 64 + n] = w1[n * 64 + k];
    }
    int t2 = t1 - 64 * 64;
    if (t2 >= 0 && t2 < 64 * 128) {
        int k = t2 >> 7, n = t2 & 127;
        g_Wt2[k * 128 + n] = w2[n * 64 + k];
    }
}

// ---------------- GEMM 0/1: 256-row tile, 256 thr, 8x8 micro-tile ------------
// smem-balanced: per k, 32B A-LDS + 32B B-LDS per 64 FMA = 1B/FMA.
// A staged at stride 68 floats (banks 0/4/8/12 across the 4 tr rows per warp).
// MODE 0: A gathered from (feat,xyz,cent,gidx); stats.      KP=68, N=64
// MODE 1: A from Y-prev, fused BN affine + ReLU; stats.     KP=64, N=64
template<int KP, int MODE>
__global__ void __launch_bounds__(256) gemm01_k(
    const float* __restrict__ A, const float* __restrict__ Wt,
    const float* __restrict__ bias,
    const float* __restrict__ fa, const float* __restrict__ fc,
    const float* __restrict__ xyz, const float* __restrict__ feat,
    float* __restrict__ Y, float* __restrict__ gs, float* __restrict__ gq)
{
    constexpr int N = 64;
    constexpr int AS = 68;               // A smem stride (floats)
    extern __shared__ float sm[];
    float* As  = sm;                     // [256][68]
    float* Bs  = sm + 256 * AS;          // [KP][64]
    float* Red = Bs + KP * N;            // [8][128]
    const int tid = threadIdx.x;
    const size_t rb = (size_t)blockIdx.x * 256;

    for (int i = tid; i < KP * N / 4; i += 256)
        ((float4*)Bs)[i] = ((const float4*)Wt)[i];

    if (MODE == 0) {
        for (int i = tid; i < 256 * 17; i += 256) {
            int r = i >> 4 == 0 ? 0 : i / 17, c4 = i - (i / 17) * 17;
            r = i / 17;
            int grow = (int)rb + r;
            int j = g_gidx[grow];
            int b = grow >> 16;
            float4 v;
            if (c4 < 16) {
                v = ((const float4*)(feat + ((size_t)(b << 13) + j) * 64))[c4];
            } else {
                const float* xp = xyz + ((size_t)(b << 13) + j) * 3;
                const float* cp = g_cent + (grow >> 5) * 3;
                v = make_float4(xp[0]-cp[0], xp[1]-cp[1], xp[2]-cp[2], 0.f);
            }
            ((float4*)(As + r * AS))[c4] = v;
        }
    } else {
        for (int i = tid; i < 256 * 16; i += 256) {
            int r = i >> 4, c = i & 15;
            float4 v = ((const float4*)(A + (rb + r) * 64))[c];
            int k = c * 4;
            v.x = fmaxf(fmaf(fa[k+0], v.x, fc[k+0]), 0.f);
            v.y = fmaxf(fmaf(fa[k+1], v.y, fc[k+1]), 0.f);
            v.z = fmaxf(fmaf(fa[k+2], v.z, fc[k+2]), 0.f);
            v.w = fmaxf(fmaf(fa[k+3], v.w, fc[k+3]), 0.f);
            ((float4*)(As + r * AS))[c] = v;
        }
    }
    __syncthreads();

    const int tc = (tid & 7) * 8;        // 8 cols
    const int tr = tid >> 3;             // 0..31; rows tr + 32*i
    float acc[8][8];
#pragma unroll
    for (int i = 0; i < 8; i++)
#pragma unroll
        for (int j = 0; j < 8; j++) acc[i][j] = bias[tc + j];

#pragma unroll 4
    for (int k = 0; k < KP; k++) {
        float av[8];
#pragma unroll
        for (int i = 0; i < 8; i++) av[i] = As[(tr + 32 * i) * AS + k];
        float bv[8];
#pragma unroll
        for (int j = 0; j < 8; j += 4) {
            float4 t = *(const float4*)&Bs[k * N + tc + j];
            bv[j] = t.x; bv[j+1] = t.y; bv[j+2] = t.z; bv[j+3] = t.w;
        }
#pragma unroll
        for (int i = 0; i < 8; i++)
#pragma unroll
            for (int j = 0; j < 8; j++) acc[i][j] = fmaf(av[i], bv[j], acc[i][j]);
    }

#pragma unroll
    for (int i = 0; i < 8; i++) {
        size_t row = rb + tr + 32 * i;
#pragma unroll
        for (int j = 0; j < 8; j += 4) {
            float4 t = make_float4(acc[i][j], acc[i][j+1], acc[i][j+2], acc[i][j+3]);
            *(float4*)&Y[row * N + tc + j] = t;
        }
    }

    // stats: sum over 8 rows, then over the 4 tr values in the warp (lanes +-8,16)
    float s[8], q[8];
#pragma unroll
    for (int j = 0; j < 8; j++) {
        float ss = 0.f, qq = 0.f;
#pragma unroll
        for (int i = 0; i < 8; i++) { float v = acc[i][j]; ss += v; qq = fmaf(v, v, qq); }
        ss += __shfl_xor_sync(0xffffffffu, ss, 8);
        qq += __shfl_xor_sync(0xffffffffu, qq, 8);
        ss += __shfl_xor_sync(0xffffffffu, ss, 16);
        qq += __shfl_xor_sync(0xffffffffu, qq, 16);
        s[j] = ss; q[j] = qq;
    }
    int w = tid >> 5, lane = tid & 31;
    if (lane < 8) {
#pragma unroll
        for (int j = 0; j < 8; j++) {
            Red[w * 128 + lane * 8 + j]      = s[j];
            Red[w * 128 + 64 + lane * 8 + j] = q[j];
        }
    }
    __syncthreads();
    if (tid < 64) {
        float ss = 0.f, qq = 0.f;
#pragma unroll
        for (int ww = 0; ww < 8; ww++) {
            ss += Red[ww * 128 + tid];
            qq += Red[ww * 128 + 64 + tid];
        }
        atomicAdd(&gs[tid], ss);
        atomicAdd(&gq[tid], qq);
    }
}

// ---------------- GEMM 2: 128x128 tile, fused max-over-K + stats -------------
__global__ void __launch_bounds__(256) gemm2_k(
    const float* __restrict__ A, const float* __restrict__ Wt,
    const float* __restrict__ bias,
    const float* __restrict__ fa, const float* __restrict__ fc,
    float* __restrict__ gs, float* __restrict__ gq)
{
    extern __shared__ float sm[];
    float* As   = sm;                    // [128][65] padded
    float* Bs   = sm + 128 * 65;         // [64][128]
    float* smax = Bs + 64 * 128;         // [8*4][128]
    float* ssum = smax + 8 * 4 * 128;    // [8][128]
    float* ssq  = ssum + 8 * 128;        // [8][128]
    const int tid = threadIdx.x;
    const size_t rb = (size_t)blockIdx.x * 128;

    for (int i = tid; i < 64 * 128 / 4; i += 256)
        ((float4*)Bs)[i] = ((const float4*)Wt)[i];

    for (int i = tid; i < 128 * 16; i += 256) {
        int r = i >> 4, c = i & 15;
        float4 v = ((const float4*)(A + (rb + r) * 64))[c];
        int k = c * 4;
        v.x = fmaxf(fmaf(fa[k+0], v.x, fc[k+0]), 0.f);
        v.y = fmaxf(fmaf(fa[k+1], v.y, fc[k+1]), 0.f);
        v.z = fmaxf(fmaf(fa[k+2], v.z, fc[k+2]), 0.f);
        v.w = fmaxf(fmaf(fa[k+3], v.w, fc[k+3]), 0.f);
        float* p = As + r * 65 + k;
        p[0] = v.x; p[1] = v.y; p[2] = v.z; p[3] = v.w;
    }
    __syncthreads();

    const int tc8 = (tid & 7) * 4;
    const int tr  = tid >> 3;            // 0..31
    float acc[4][16];
#pragma unroll
    for (int c = 0; c < 4; c++)
#pragma unroll
        for (int j = 0; j < 4; j++) {
            float bb = bias[tc8 + j + 32 * c];
#pragma unroll
            for (int m = 0; m < 4; m++) acc[m][c*4+j] = bb;
        }

#pragma unroll 4
    for (int k = 0; k < 64; k++) {
        float av[4];
#pragma unroll
        for (int m = 0; m < 4; m++) av[m] = As[(tr + 32*m) * 65 + k];
        float bv[16];
#pragma unroll
        for (int c = 0; c < 4; c++) {
            float4 t = *(const float4*)&Bs[k * 128 + tc8 + 32 * c];
            bv[c*4+0] = t.x; bv[c*4+1] = t.y; bv[c*4+2] = t.z; bv[c*4+3] = t.w;
        }
#pragma unroll
        for (int m = 0; m < 4; m++)
#pragma unroll
            for (int j = 0; j < 16; j++) acc[m][j] = fmaf(av[m], bv[j], acc[m][j]);
    }

    float s[16], q[16];
#pragma unroll
    for (int j = 0; j < 16; j++) {
        s[j] = acc[0][j] + acc[1][j] + acc[2][j] + acc[3][j];
        q[j] = fmaf(acc[0][j], acc[0][j], fmaf(acc[1][j], acc[1][j],
               fmaf(acc[2][j], acc[2][j], acc[3][j] * acc[3][j])));
    }
#pragma unroll
    for (int j = 0; j < 16; j++) {
#pragma unroll
        for (int m = 0; m < 4; m++) {
            acc[m][j] = fmaxf(acc[m][j], __shfl_xor_sync(0xffffffffu, acc[m][j], 8));
            acc[m][j] = fmaxf(acc[m][j], __shfl_xor_sync(0xffffffffu, acc[m][j], 16));
        }
        s[j] += __shfl_xor_sync(0xffffffffu, s[j], 8);
        s[j] += __shfl_xor_sync(0xffffffffu, s[j], 16);
        q[j] += __shfl_xor_sync(0xffffffffu, q[j], 8);
        q[j] += __shfl_xor_sync(0xffffffffu, q[j], 16);
    }
    int w = tid >> 5, lane = tid & 31;
    if (lane < 8) {
#pragma unroll
        for (int c = 0; c < 4; c++)
#pragma unroll
            for (int j = 0; j < 4; j++) {
                int col = lane * 4 + j + 32 * c;
#pragma unroll
                for (int m = 0; m < 4; m++) smax[(w*4 + m) * 128 + col] = acc[m][c*4+j];
                ssum[w * 128 + col] = s[c*4+j];
                ssq[w * 128 + col]  = q[c*4+j];
            }
    }
    __syncthreads();
    for (int cell = tid; cell < 512; cell += 256) {
        int m = cell >> 7, col = cell & 127;
        float v = smax[m * 128 + col];
#pragma unroll
        for (int ww = 1; ww < 8; ww++) v = fmaxf(v, smax[(ww*4 + m) * 128 + col]);
        g_maxraw[((size_t)blockIdx.x * 4 + m) * 128 + col] = v;
    }
    if (tid < 128) {
        float ss = 0.f, qq = 0.f;
#pragma unroll
        for (int ww = 0; ww < 8; ww++) { ss += ssum[ww*128 + tid]; qq += ssq[ww*128 + tid]; }
        atomicAdd(&gs[tid], ss);
        atomicAdd(&gq[tid], qq);
    }
}

// ---------------- BN affine finalize -----------------------------------------
__global__ void finalize_k(const float* __restrict__ s, const float* __restrict__ q,
                           const float* __restrict__ g, const float* __restrict__ beta,
                           float* __restrict__ fa, float* __restrict__ fc, int n) {
    int i = blockIdx.x * 64 + threadIdx.x;
    if (i < n) {
        const float inv = 1.0f / 524288.0f;
        float m = s[i] * inv;
        float var = q[i] * inv - m * m;
        float a = g[i] * rsqrtf(var + 1e-5f);
        fa[i] = a;
        fc[i] = fmaf(-m, a, beta[i]);
    }
}

// ---------------- final output ------------------------------------------------
__global__ void out_k(float* __restrict__ out) {
    int id = blockIdx.x * 256 + threadIdx.x;
    int c = id & 127;
    out[id] = fmaxf(fmaf(g_a2[c], g_maxraw[id], g_c2[c]), 0.f);
}

// ---------------- launch ------------------------------------------------------
extern "C" void kernel_launch(void* const* d_in, const int* in_sizes, int n_in,
                              void* d_out, int out_size) {
    const float* xyz  = (const float*)d_in[0];
    const float* feat = (const float*)d_in[1];
    const float* w0 = (const float*)d_in[2],  *b0 = (const float*)d_in[3];
    const float* g0 = (const float*)d_in[4],  *be0 = (const float*)d_in[5];
    const float* w1 = (const float*)d_in[6],  *b1 = (const float*)d_in[7];
    const float* g1 = (const float*)d_in[8],  *be1 = (const float*)d_in[9];
    const float* w2 = (const float*)d_in[10], *b2 = (const float*)d_in[11];
    const float* g2 = (const float*)d_in[12], *be2 = (const float*)d_in[13];
    float* out = (float*)d_out;

    float *ds0,*dq0,*ds1,*dq1,*ds2,*dq2,*da0,*dc0,*da1,*dc1,*da2,*dc2;
    cudaGetSymbolAddress((void**)&ds0, g_s0); cudaGetSymbolAddress((void**)&dq0, g_q0);
    cudaGetSymbolAddress((void**)&ds1, g_s1); cudaGetSymbolAddress((void**)&dq1, g_q1);
    cudaGetSymbolAddress((void**)&ds2, g_s2); cudaGetSymbolAddress((void**)&dq2, g_q2);
    cudaGetSymbolAddress((void**)&da0, g_a0); cudaGetSymbolAddress((void**)&dc0, g_c0);
    cudaGetSymbolAddress((void**)&da1, g_a1); cudaGetSymbolAddress((void**)&dc1, g_c1);
    cudaGetSymbolAddress((void**)&da2, g_a2); cudaGetSymbolAddress((void**)&dc2, g_c2);
    float *dy0,*dy1,*dWt0,*dWt1,*dWt2;
    cudaGetSymbolAddress((void**)&dy0, g_y0);
    cudaGetSymbolAddress((void**)&dy1, g_y1);
    cudaGetSymbolAddress((void**)&dWt0, g_Wt0);
    cudaGetSymbolAddress((void**)&dWt1, g_Wt1);
    cudaGetSymbolAddress((void**)&dWt2, g_Wt2);

    const int smemF = 24576 * 4;                       // fps
    const int smemB = 24576 * 4 + 512 * 4;             // ballq
    const int smem0 = (256*68 + 68*64 + 8*128) * 4;    // 91136
    const int smem1 = (256*68 + 64*64 + 8*128) * 4;    // 87040
    const int smem2 = (128*65 + 64*128 + 8*4*128 + 2*8*128) * 4; // 90624
    cudaFuncSetAttribute(fps_k,   cudaFuncAttributeMaxDynamicSharedMemorySize, smemF);
    cudaFuncSetAttribute(ballq_k, cudaFuncAttributeMaxDynamicSharedMemorySize, smemB);
    cudaFuncSetAttribute(gemm01_k<68,0>, cudaFuncAttributeMaxDynamicSharedMemorySize, smem0);
    cudaFuncSetAttribute(gemm01_k<64,1>, cudaFuncAttributeMaxDynamicSharedMemorySize, smem1);
    cudaFuncSetAttribute(gemm2_k,        cudaFuncAttributeMaxDynamicSharedMemorySize, smem2);

    zero_k<<<1, 128>>>();
    fps_k<<<8, 1024, smemF>>>(xyz);
    centroid_k<<<64, 256>>>(xyz, out);                 // out[0..49151] = centroids
    ballq_k<<<1024, 512, smemB>>>(xyz);
    prepw_k<<<65, 256>>>(w0, w1, w2);
    gemm01_k<68,0><<<2048, 256, smem0>>>(nullptr, dWt0, b0, nullptr, nullptr,
                                         xyz, feat, dy0, ds0, dq0);
    finalize_k<<<1, 64>>>(ds0, dq0, g0, be0, da0, dc0, 64);
    gemm01_k<64,1><<<2048, 256, smem1>>>(dy0, dWt1, b1, da0, dc0,
                                         nullptr, nullptr, dy1, ds1, dq1);
    finalize_k<<<1, 64>>>(ds1, dq1, g1, be1, da1, dc1, 64);
    gemm2_k<<<4096, 256, smem2>>>(dy1, dWt2, b2, da1, dc1, ds2, dq2);
    finalize_k<<<2, 64>>>(ds2, dq2, g2, be2, da2, dc2, 128);
    out_k<<<8192, 256>>>(out + 49152);
}

// round 15
// speedup vs baseline: 1.5368x; 1.0810x over previous
#include <cuda_runtime.h>
#include <cuda_bf16.h>
#include <cstdint>

typedef unsigned long long ULL;

// ---------------- scratch (static device globals; no allocation) ------------
__device__ float g_P[65536 * 64];        // layer0 per-point: W0@[feat;xyz]+b0
__device__ float g_C[16384 * 64];        // per-centroid: W0xyz@cent
__device__ float g_y1[524288 * 64];
__device__ float g_maxraw[16384 * 128];
__device__ int   g_fpsidx[16384];
__device__ float g_cent[16384 * 3];
__device__ int   g_gidx[524288];
__device__ float g_Wt0[68 * 64];
__device__ float g_Wt1[64 * 64];
__device__ float g_Wt2[64 * 128];
__device__ float g_s0[64], g_q0[64], g_s1[64], g_q1[64], g_s2[128], g_q2[128];
__device__ float g_a0[64], g_c0[64], g_a1[64], g_c1[64], g_a2[128], g_c2[128];

// ---------------- helpers ---------------------------------------------------
__device__ __forceinline__ ULL packf2(float lo, float hi) {
    ULL r; unsigned a = __float_as_uint(lo), b = __float_as_uint(hi);
    asm("mov.b64 %0,{%1,%2};" : "=l"(r) : "r"(a), "r"(b)); return r;
}
__device__ __forceinline__ float2 unpackf2(ULL v) {
    unsigned a, b; asm("mov.b64 {%0,%1},%2;" : "=r"(a), "=r"(b) : "l"(v));
    return make_float2(__uint_as_float(a), __uint_as_float(b));
}
__device__ __forceinline__ ULL f2add(ULL a, ULL b) {
    ULL r; asm("add.rn.f32x2 %0,%1,%2;" : "=l"(r) : "l"(a), "l"(b)); return r;
}
__device__ __forceinline__ ULL f2mul(ULL a, ULL b) {
    ULL r; asm("mul.rn.f32x2 %0,%1,%2;" : "=l"(r) : "l"(a), "l"(b)); return r;
}
__device__ __forceinline__ float d2_noFMA(float dx, float dy, float dz) {
    return __fadd_rn(__fadd_rn(__fmul_rn(dx, dx), __fmul_rn(dy, dy)), __fmul_rn(dz, dz));
}

// ---------------- zero stats -------------------------------------------------
__global__ void zero_k() {
    int t = threadIdx.x;
    if (t < 64) { g_s0[t]=0.f; g_q0[t]=0.f; g_s1[t]=0.f; g_q1[t]=0.f; }
    if (t < 128){ g_s2[t]=0.f; g_q2[t]=0.f; }
}

// ---------------- FPS: 1 CTA/batch, 1024 thr, 8 pts/thread, 1 barrier -------
__global__ void __launch_bounds__(1024) fps_k(const float* __restrict__ xyz) {
    extern __shared__ float sx[];                      // 24576 floats
    __shared__ unsigned swhi[2][32], swlo[2][32];
    const int b = blockIdx.x, tid = threadIdx.x, wid = tid >> 5, lane = tid & 31;
    const float* X = xyz + (size_t)b * 24576;

    for (int i = tid; i < 6144; i += 1024)
        ((float4*)sx)[i] = ((const float4*)X)[i];
    __syncthreads();

    ULL px[4], py[4], pz[4]; float dist[8];
#pragma unroll
    for (int j = 0; j < 4; j++) {
        int p0 = tid + 2048 * j, p1 = p0 + 1024;
        px[j] = packf2(sx[3*p0+0], sx[3*p1+0]);
        py[j] = packf2(sx[3*p0+1], sx[3*p1+1]);
        pz[j] = packf2(sx[3*p0+2], sx[3*p1+2]);
        dist[2*j] = 1e10f; dist[2*j+1] = 1e10f;
    }
    float cx = sx[0], cy = sx[1], cz = sx[2];
    if (tid == 0) g_fpsidx[b * 2048] = 0;

    for (int s = 1; s < 2048; s++) {
        const int pb = s & 1;
        ULL ncx = packf2(-cx, -cx), ncy = packf2(-cy, -cy), ncz = packf2(-cz, -cz);
        float m8 = 0.0f;
#pragma unroll
        for (int j = 0; j < 4; j++) {
            ULL dx = f2add(px[j], ncx);
            ULL dy = f2add(py[j], ncy);
            ULL dz = f2add(pz[j], ncz);
            // mul/add tree, no FMA: matches reference rounding exactly
            ULL d2 = f2add(f2add(f2mul(dx, dx), f2mul(dy, dy)), f2mul(dz, dz));
            float2 d = unpackf2(d2);
            float a = fminf(dist[2*j],   d.x); dist[2*j]   = a;
            float c = fminf(dist[2*j+1], d.y); dist[2*j+1] = c;
            m8 = fmaxf(m8, fmaxf(a, c));
        }
        unsigned mb = __float_as_uint(m8);               // dists >= 0: bit-monotone
        unsigned wm = __reduce_max_sync(0xffffffffu, mb);
        unsigned cand = 0xffffffffu;                     // cand == point index
        if (mb == wm) {
#pragma unroll
            for (int i = 0; i < 8; i++) {
                if (__float_as_uint(dist[i]) == wm) { cand = (unsigned)(tid + (i << 10)); break; }
            }
        }
        unsigned cmin = __reduce_min_sync(0xffffffffu, cand);
        if (lane == 0) { swhi[pb][wid] = wm; swlo[pb][wid] = cmin; }
        __syncthreads();
        unsigned hi = swhi[pb][lane];
        unsigned lo = swlo[pb][lane];
        unsigned hm = __reduce_max_sync(0xffffffffu, hi);
        unsigned p  = __reduce_min_sync(0xffffffffu, (hi == hm) ? lo : 0xffffffffu);
        if (tid == 0) g_fpsidx[b * 2048 + s] = (int)p;
        cx = sx[3*p]; cy = sx[3*p+1]; cz = sx[3*p+2];
    }
}

// ---------------- centroids --------------------------------------------------
__global__ void centroid_k(const float* __restrict__ xyz, float* __restrict__ outc) {
    int id = blockIdx.x * 256 + threadIdx.x;
    if (id >= 16384) return;
    int b = id >> 11;
    int p = g_fpsidx[id];
    const float* src = xyz + ((size_t)(b << 13) + p) * 3;
    float x = src[0], y = src[1], z = src[2];
    outc[id*3+0] = x; outc[id*3+1] = y; outc[id*3+2] = z;
    g_cent[id*3+0] = x; g_cent[id*3+1] = y; g_cent[id*3+2] = z;
}

// ---------------- ball query: smem-staged, warp per centroid -----------------
__global__ void __launch_bounds__(512) ballq_k(const float* __restrict__ xyz) {
    extern __shared__ float sb[];
    int* sidx = (int*)(sb + 24576);
    int tid = threadIdx.x, wid = tid >> 5, lane = tid & 31;
    int cid = blockIdx.x * 16 + wid;
    int b = cid >> 11;
    const float* X = xyz + (size_t)b * 24576;
    for (int i = tid; i < 6144; i += 512)
        ((float4*)sb)[i] = ((const float4*)X)[i];
    float cx = g_cent[cid*3], cy = g_cent[cid*3+1], cz = g_cent[cid*3+2];
    __syncthreads();

    int cnt = 0;
    for (int base = 0; base < 8192; base += 32) {
        int j = base + lane;
        float d2 = d2_noFMA(cx - sb[3*j], cy - sb[3*j+1], cz - sb[3*j+2]);
        bool hit = d2 <= 0.04f;
        unsigned m = __ballot_sync(0xffffffffu, hit);
        if (m) {
            int r = __popc(m & ((1u << lane) - 1u));
            if (hit && cnt + r < 32) sidx[wid*32 + cnt + r] = j;
            cnt += __popc(m);
            if (cnt >= 32) break;
        }
    }
    __syncwarp();
    int first = sidx[wid*32];
    int c = cnt < 32 ? cnt : 32;
    g_gidx[cid * 32 + lane] = (lane < c) ? sidx[wid*32 + lane] : first;
}

// ---------------- weight transpose (k-major) ---------------------------------
__global__ void prepw_k(const float* __restrict__ w0, const float* __restrict__ w1,
                        const float* __restrict__ w2) {
    int t = blockIdx.x * 256 + threadIdx.x;
    if (t < 68 * 64) {
        int k = t >> 6, n = t & 63;
        float v = 0.f;
        if (k < 64) v = w0[n * 67 + 3 + k];
        else if (k < 67) v = w0[n * 67 + (k - 64)];
        g_Wt0[k * 64 + n] = v;
    }
    int t1 = t - 68 * 64;
    if (t1 >= 0 && t1 < 64 * 64) {
        int k = t1 >> 6, n = t1 & 63;
        g_Wt1[k * 64 + n] = w1[n * 64 + k];
    }
    int t2 = t1 - 64 * 64;
    if (t2 >= 0 && t2 < 64 * 128) {
        int k = t2 >> 7, n = t2 & 127;
        g_Wt2[k * 128 + n] = w2[n * 64 + k];
    }
}

// ---------------- centroid projection: C[s] = W0xyz @ cent_s -----------------
__global__ void __launch_bounds__(256) centproj_k(const float* __restrict__ w0) {
    __shared__ float sw[192];                 // w0[n][0..2] for n 0..63
    int tid = threadIdx.x;
    if (tid < 192) sw[tid] = w0[(tid / 3) * 67 + (tid % 3)];
    __syncthreads();
    int id = blockIdx.x * 256 + tid;          // 0..1048575
    int s = id >> 6, n = id & 63;
    const float* cp = g_cent + s * 3;
    g_C[id] = sw[n*3+0] * cp[0] + sw[n*3+1] * cp[1] + sw[n*3+2] * cp[2];
}

// ---------------- layer-0 stats over virtual y0 = P[j] - C[s] ----------------
__global__ void __launch_bounds__(256) stats0_k(const float* __restrict__ P,
                                                const float* __restrict__ C,
                                                float* __restrict__ gs,
                                                float* __restrict__ gq) {
    __shared__ float S[4][64], Q[4][64];
    int c = threadIdx.x & 63, rr = threadIdx.x >> 6;   // rr 0..3
    int base = blockIdx.x * 256;
    float s = 0.f, q = 0.f;
#pragma unroll 4
    for (int it = 0; it < 64; it++) {
        int row = base + it * 4 + rr;
        int j = g_gidx[row];
        int b = row >> 16;
        float v = P[(size_t)((b << 13) + j) * 64 + c] - C[(size_t)(row >> 5) * 64 + c];
        s += v; q = fmaf(v, v, q);
    }
    S[rr][c] = s; Q[rr][c] = q;
    __syncthreads();
    if (rr == 0) {
        float ss = S[0][c] + S[1][c] + S[2][c] + S[3][c];
        float qq = Q[0][c] + Q[1][c] + Q[2][c] + Q[3][c];
        atomicAdd(&gs[c], ss);
        atomicAdd(&gq[c], qq);
    }
}

// ---------------- GEMM: 256-row tile, 256 thr, 8x8 micro-tile ----------------
// MODE 0: P-build over points: A = [feat_j ; xyz_j ; pad], no stats. KP=68
// MODE 2: A = relu(affine(P[gidx[row]] - C[row>>5])), stats.        KP=64
template<int KP, int MODE>
__global__ void __launch_bounds__(256) gemm01_k(
    const float* __restrict__ A, const float* __restrict__ Wt,
    const float* __restrict__ bias,
    const float* __restrict__ fa, const float* __restrict__ fc,
    const float* __restrict__ xyz, const float* __restrict__ feat,
    float* __restrict__ Y, float* __restrict__ gs, float* __restrict__ gq)
{
    constexpr int N = 64;
    constexpr int AS = 68;               // A smem stride (floats)
    extern __shared__ float sm[];
    float* As  = sm;                     // [256][68]
    float* Bs  = sm + 256 * AS;          // [KP][64]
    float* Red = Bs + KP * N;            // [8][128] (MODE 2)
    const int tid = threadIdx.x;
    const size_t rb = (size_t)blockIdx.x * 256;

    for (int i = tid; i < KP * N / 4; i += 256)
        ((float4*)Bs)[i] = ((const float4*)Wt)[i];

    if (MODE == 0) {
        // rows = global point ids; 17 float4 chunks (16 feat + 1 raw-xyz/pad)
        for (int i = tid; i < 256 * 17; i += 256) {
            int r = i / 17, c4 = i - r * 17;
            int j = (int)rb + r;
            float4 v;
            if (c4 < 16) {
                v = ((const float4*)(feat + (size_t)j * 64))[c4];
            } else {
                const float* xp = xyz + (size_t)j * 3;
                v = make_float4(xp[0], xp[1], xp[2], 0.f);
            }
            ((float4*)(As + r * AS))[c4] = v;
        }
    } else {
        for (int i = tid; i < 256 * 16; i += 256) {
            int r = i >> 4, c = i & 15;
            int row = (int)rb + r;
            int j = g_gidx[row];
            int b = row >> 16;
            float4 v = ((const float4*)(A + (size_t)((b << 13) + j) * 64))[c];
            float4 u = ((const float4*)(g_C + (size_t)(row >> 5) * 64))[c];
            v.x -= u.x; v.y -= u.y; v.z -= u.z; v.w -= u.w;
            int k = c * 4;
            v.x = fmaxf(fmaf(fa[k+0], v.x, fc[k+0]), 0.f);
            v.y = fmaxf(fmaf(fa[k+1], v.y, fc[k+1]), 0.f);
            v.z = fmaxf(fmaf(fa[k+2], v.z, fc[k+2]), 0.f);
            v.w = fmaxf(fmaf(fa[k+3], v.w, fc[k+3]), 0.f);
            ((float4*)(As + r * AS))[c] = v;
        }
    }
    __syncthreads();

    const int tc = (tid & 7) * 8;        // 8 cols
    const int tr = tid >> 3;             // 0..31; rows tr + 32*i
    float acc[8][8];
#pragma unroll
    for (int i = 0; i < 8; i++)
#pragma unroll
        for (int j = 0; j < 8; j++) acc[i][j] = bias[tc + j];

#pragma unroll 4
    for (int k = 0; k < KP; k++) {
        float av[8];
#pragma unroll
        for (int i = 0; i < 8; i++) av[i] = As[(tr + 32 * i) * AS + k];
        float bv[8];
#pragma unroll
        for (int j = 0; j < 8; j += 4) {
            float4 t = *(const float4*)&Bs[k * N + tc + j];
            bv[j] = t.x; bv[j+1] = t.y; bv[j+2] = t.z; bv[j+3] = t.w;
        }
#pragma unroll
        for (int i = 0; i < 8; i++)
#pragma unroll
            for (int j = 0; j < 8; j++) acc[i][j] = fmaf(av[i], bv[j], acc[i][j]);
    }

#pragma unroll
    for (int i = 0; i < 8; i++) {
        size_t row = rb + tr + 32 * i;
#pragma unroll
        for (int j = 0; j < 8; j += 4) {
            float4 t = make_float4(acc[i][j], acc[i][j+1], acc[i][j+2], acc[i][j+3]);
            *(float4*)&Y[row * N + tc + j] = t;
        }
    }

    if (MODE == 2) {
        float s[8], q[8];
#pragma unroll
        for (int j = 0; j < 8; j++) {
            float ss = 0.f, qq = 0.f;
#pragma unroll
            for (int i = 0; i < 8; i++) { float v = acc[i][j]; ss += v; qq = fmaf(v, v, qq); }
            ss += __shfl_xor_sync(0xffffffffu, ss, 8);
            qq += __shfl_xor_sync(0xffffffffu, qq, 8);
            ss += __shfl_xor_sync(0xffffffffu, ss, 16);
            qq += __shfl_xor_sync(0xffffffffu, qq, 16);
            s[j] = ss; q[j] = qq;
        }
        int w = tid >> 5, lane = tid & 31;
        if (lane < 8) {
#pragma unroll
            for (int j = 0; j < 8; j++) {
                Red[w * 128 + lane * 8 + j]      = s[j];
                Red[w * 128 + 64 + lane * 8 + j] = q[j];
            }
        }
        __syncthreads();
        if (tid < 64) {
            float ss = 0.f, qq = 0.f;
#pragma unroll
            for (int ww = 0; ww < 8; ww++) {
                ss += Red[ww * 128 + tid];
                qq += Red[ww * 128 + 64 + tid];
            }
            atomicAdd(&gs[tid], ss);
            atomicAdd(&gq[tid], qq);
        }
    }
}

// ---------------- GEMM 2: 128x128 tile, fused max-over-K + stats -------------
__global__ void __launch_bounds__(256) gemm2_k(
    const float* __restrict__ A, const float* __restrict__ Wt,
    const float* __restrict__ bias,
    const float* __restrict__ fa, const float* __restrict__ fc,
    float* __restrict__ gs, float* __restrict__ gq)
{
    extern __shared__ float sm[];
    float* As   = sm;                    // [128][65] padded
    float* Bs   = sm + 128 * 65;         // [64][128]
    float* smax = Bs + 64 * 128;         // [8*4][128]
    float* ssum = smax + 8 * 4 * 128;    // [8][128]
    float* ssq  = ssum + 8 * 128;        // [8][128]
    const int tid = threadIdx.x;
    const size_t rb = (size_t)blockIdx.x * 128;

    for (int i = tid; i < 64 * 128 / 4; i += 256)
        ((float4*)Bs)[i] = ((const float4*)Wt)[i];

    for (int i = tid; i < 128 * 16; i += 256) {
        int r = i >> 4, c = i & 15;
        float4 v = ((const float4*)(A + (rb + r) * 64))[c];
        int k = c * 4;
        v.x = fmaxf(fmaf(fa[k+0], v.x, fc[k+0]), 0.f);
        v.y = fmaxf(fmaf(fa[k+1], v.y, fc[k+1]), 0.f);
        v.z = fmaxf(fmaf(fa[k+2], v.z, fc[k+2]), 0.f);
        v.w = fmaxf(fmaf(fa[k+3], v.w, fc[k+3]), 0.f);
        float* p = As + r * 65 + k;
        p[0] = v.x; p[1] = v.y; p[2] = v.z; p[3] = v.w;
    }
    __syncthreads();

    const int tc8 = (tid & 7) * 4;
    const int tr  = tid >> 3;            // 0..31
    float acc[4][16];
#pragma unroll
    for (int c = 0; c < 4; c++)
#pragma unroll
        for (int j = 0; j < 4; j++) {
            float bb = bias[tc8 + j + 32 * c];
#pragma unroll
            for (int m = 0; m < 4; m++) acc[m][c*4+j] = bb;
        }

#pragma unroll 4
    for (int k = 0; k < 64; k++) {
        float av[4];
#pragma unroll
        for (int m = 0; m < 4; m++) av[m] = As[(tr + 32*m) * 65 + k];
        float bv[16];
#pragma unroll
        for (int c = 0; c < 4; c++) {
            float4 t = *(const float4*)&Bs[k * 128 + tc8 + 32 * c];
            bv[c*4+0] = t.x; bv[c*4+1] = t.y; bv[c*4+2] = t.z; bv[c*4+3] = t.w;
        }
#pragma unroll
        for (int m = 0; m < 4; m++)
#pragma unroll
            for (int j = 0; j < 16; j++) acc[m][j] = fmaf(av[m], bv[j], acc[m][j]);
    }

    float s[16], q[16];
#pragma unroll
    for (int j = 0; j < 16; j++) {
        s[j] = acc[0][j] + acc[1][j] + acc[2][j] + acc[3][j];
        q[j] = fmaf(acc[0][j], acc[0][j], fmaf(acc[1][j], acc[1][j],
               fmaf(acc[2][j], acc[2][j], acc[3][j] * acc[3][j])));
    }
#pragma unroll
    for (int j = 0; j < 16; j++) {
#pragma unroll
        for (int m = 0; m < 4; m++) {
            acc[m][j] = fmaxf(acc[m][j], __shfl_xor_sync(0xffffffffu, acc[m][j], 8));
            acc[m][j] = fmaxf(acc[m][j], __shfl_xor_sync(0xffffffffu, acc[m][j], 16));
        }
        s[j] += __shfl_xor_sync(0xffffffffu, s[j], 8);
        s[j] += __shfl_xor_sync(0xffffffffu, s[j], 16);
        q[j] += __shfl_xor_sync(0xffffffffu, q[j], 8);
        q[j] += __shfl_xor_sync(0xffffffffu, q[j], 16);
    }
    int w = tid >> 5, lane = tid & 31;
    if (lane < 8) {
#pragma unroll
        for (int c = 0; c < 4; c++)
#pragma unroll
            for (int j = 0; j < 4; j++) {
                int col = lane * 4 + j + 32 * c;
#pragma unroll
                for (int m = 0; m < 4; m++) smax[(w*4 + m) * 128 + col] = acc[m][c*4+j];
                ssum[w * 128 + col] = s[c*4+j];
                ssq[w * 128 + col]  = q[c*4+j];
            }
    }
    __syncthreads();
    for (int cell = tid; cell < 512; cell += 256) {
        int m = cell >> 7, col = cell & 127;
        float v = smax[m * 128 + col];
#pragma unroll
        for (int ww = 1; ww < 8; ww++) v = fmaxf(v, smax[(ww*4 + m) * 128 + col]);
        g_maxraw[((size_t)blockIdx.x * 4 + m) * 128 + col] = v;
    }
    if (tid < 128) {
        float ss = 0.f, qq = 0.f;
#pragma unroll
        for (int ww = 0; ww < 8; ww++) { ss += ssum[ww*128 + tid]; qq += ssq[ww*128 + tid]; }
        atomicAdd(&gs[tid], ss);
        atomicAdd(&gq[tid], qq);
    }
}

// ---------------- BN affine finalize -----------------------------------------
__global__ void finalize_k(const float* __restrict__ s, const float* __restrict__ q,
                           const float* __restrict__ g, const float* __restrict__ beta,
                           float* __restrict__ fa, float* __restrict__ fc, int n) {
    int i = blockIdx.x * 64 + threadIdx.x;
    if (i < n) {
        const float inv = 1.0f / 524288.0f;
        float m = s[i] * inv;
        float var = q[i] * inv - m * m;
        float a = g[i] * rsqrtf(var + 1e-5f);
        fa[i] = a;
        fc[i] = fmaf(-m, a, beta[i]);
    }
}

// ---------------- final output ------------------------------------------------
__global__ void out_k(float* __restrict__ out) {
    int id = blockIdx.x * 256 + threadIdx.x;
    int c = id & 127;
    out[id] = fmaxf(fmaf(g_a2[c], g_maxraw[id], g_c2[c]), 0.f);
}

// ---------------- launch ------------------------------------------------------
extern "C" void kernel_launch(void* const* d_in, const int* in_sizes, int n_in,
                              void* d_out, int out_size) {
    const float* xyz  = (const float*)d_in[0];
    const float* feat = (const float*)d_in[1];
    const float* w0 = (const float*)d_in[2],  *b0 = (const float*)d_in[3];
    const float* g0 = (const float*)d_in[4],  *be0 = (const float*)d_in[5];
    const float* w1 = (const float*)d_in[6],  *b1 = (const float*)d_in[7];
    const float* g1 = (const float*)d_in[8],  *be1 = (const float*)d_in[9];
    const float* w2 = (const float*)d_in[10], *b2 = (const float*)d_in[11];
    const float* g2 = (const float*)d_in[12], *be2 = (const float*)d_in[13];
    float* out = (float*)d_out;

    float *ds0,*dq0,*ds1,*dq1,*ds2,*dq2,*da0,*dc0,*da1,*dc1,*da2,*dc2;
    cudaGetSymbolAddress((void**)&ds0, g_s0); cudaGetSymbolAddress((void**)&dq0, g_q0);
    cudaGetSymbolAddress((void**)&ds1, g_s1); cudaGetSymbolAddress((void**)&dq1, g_q1);
    cudaGetSymbolAddress((void**)&ds2, g_s2); cudaGetSymbolAddress((void**)&dq2, g_q2);
    cudaGetSymbolAddress((void**)&da0, g_a0); cudaGetSymbolAddress((void**)&dc0, g_c0);
    cudaGetSymbolAddress((void**)&da1, g_a1); cudaGetSymbolAddress((void**)&dc1, g_c1);
    cudaGetSymbolAddress((void**)&da2, g_a2); cudaGetSymbolAddress((void**)&dc2, g_c2);
    float *dP,*dC,*dy1,*dWt0,*dWt1,*dWt2;
    cudaGetSymbolAddress((void**)&dP, g_P);
    cudaGetSymbolAddress((void**)&dC, g_C);
    cudaGetSymbolAddress((void**)&dy1, g_y1);
    cudaGetSymbolAddress((void**)&dWt0, g_Wt0);
    cudaGetSymbolAddress((void**)&dWt1, g_Wt1);
    cudaGetSymbolAddress((void**)&dWt2, g_Wt2);

    const int smemF = 24576 * 4;                       // fps
    const int smemB = 24576 * 4 + 512 * 4;             // ballq
    const int smemP = (256*68 + 68*64) * 4;            // 87040 (P build)
    const int smem1 = (256*68 + 64*64 + 8*128) * 4;    // 90112
    const int smem2 = (128*65 + 64*128 + 8*4*128 + 2*8*128) * 4; // 90624
    cudaFuncSetAttribute(fps_k,   cudaFuncAttributeMaxDynamicSharedMemorySize, smemF);
    cudaFuncSetAttribute(ballq_k, cudaFuncAttributeMaxDynamicSharedMemorySize, smemB);
    cudaFuncSetAttribute(gemm01_k<68,0>, cudaFuncAttributeMaxDynamicSharedMemorySize, smemP);
    cudaFuncSetAttribute(gemm01_k<64,2>, cudaFuncAttributeMaxDynamicSharedMemorySize, smem1);
    cudaFuncSetAttribute(gemm2_k,        cudaFuncAttributeMaxDynamicSharedMemorySize, smem2);

    zero_k<<<1, 128>>>();
    fps_k<<<8, 1024, smemF>>>(xyz);
    centroid_k<<<64, 256>>>(xyz, out);                 // out[0..49151] = centroids
    ballq_k<<<1024, 512, smemB>>>(xyz);
    prepw_k<<<65, 256>>>(w0, w1, w2);
    // P[j] = W0 @ [feat_j ; xyz_j] + b0 over 65536 points
    gemm01_k<68,0><<<256, 256, smemP>>>(nullptr, dWt0, b0, nullptr, nullptr,
                                        xyz, feat, dP, nullptr, nullptr);
    centproj_k<<<4096, 256>>>(w0);                     // C[s] = W0xyz @ cent_s
    stats0_k<<<2048, 256>>>(dP, dC, ds0, dq0);         // BN0 stats over P[j]-C[s]
    finalize_k<<<1, 64>>>(ds0, dq0, g0, be0, da0, dc0, 64);
    gemm01_k<64,2><<<2048, 256, smem1>>>(dP, dWt1, b1, da0, dc0,
                                         nullptr, nullptr, dy1, ds1, dq1);
    finalize_k<<<1, 64>>>(ds1, dq1, g1, be1, da1, dc1, 64);
    gemm2_k<<<4096, 256, smem2>>>(dy1, dWt2, b2, da1, dc1, ds2, dq2);
    finalize_k<<<2, 64>>>(ds2, dq2, g2, be2, da2, dc2, 128);
    out_k<<<8192, 256>>>(out + 49152);
}